// round 1
// baseline (speedup 1.0000x reference)
#include <cuda_runtime.h>
#include <math.h>

#define Bb 16
#define Pp 1024
#define Ee 1024
#define Hh 16
#define Dh 64

// 64 MB scratch each — device globals (allocation-free per harness rules)
__device__ float g_vx[(size_t)Bb * Pp * Ee];
__device__ float g_att[(size_t)Bb * Pp * Ee];

// XOR swizzle on 4-float chunks within a 64-float row: keeps float4 reads
// conflict-free while reducing transposed scalar stores from 16-way to 2-way.
__device__ __forceinline__ int swz(int row, int col) {
    return (row << 6) + ((((col >> 2) ^ (row >> 2)) & 15) << 2) + (col & 3);
}

// C[M,N] = A[M,K] @ B[N,K]^T + bias[N]   (both A and B row-major, K contiguous)
__global__ void __launch_bounds__(256) gemm_nt_bias(
    const float* __restrict__ A, const float* __restrict__ Bw,
    const float* __restrict__ bias, float* __restrict__ C,
    int M, int N, int K)
{
    __shared__ float As[8][128];
    __shared__ float Bs[8][128];
    const int tid = threadIdx.x;
    const int tx = tid & 15;
    const int ty = tid >> 4;
    const int lr = tid >> 1;
    const int lc = (tid & 1) << 2;

    const float* Ap = A + (size_t)(blockIdx.y * 128 + lr) * K + lc;
    const float* Bp = Bw + (size_t)(blockIdx.x * 128 + lr) * K + lc;

    float acc[8][8];
#pragma unroll
    for (int i = 0; i < 8; i++)
#pragma unroll
        for (int j = 0; j < 8; j++) acc[i][j] = 0.f;

    for (int k0 = 0; k0 < K; k0 += 8) {
        float4 av = *(const float4*)(Ap + k0);
        float4 bv = *(const float4*)(Bp + k0);
        As[lc + 0][lr] = av.x;
        As[lc + 1][lr] = av.y;
        As[lc + 2][lr] = av.z;
        As[lc + 3][lr] = av.w;
        Bs[lc + 0][lr] = bv.x;
        Bs[lc + 1][lr] = bv.y;
        Bs[lc + 2][lr] = bv.z;
        Bs[lc + 3][lr] = bv.w;
        __syncthreads();
#pragma unroll
        for (int kk = 0; kk < 8; kk++) {
            float a[8], b[8];
            *(float4*)(a)     = *(const float4*)(&As[kk][ty * 8]);
            *(float4*)(a + 4) = *(const float4*)(&As[kk][ty * 8 + 4]);
            *(float4*)(b)     = *(const float4*)(&Bs[kk][tx * 8]);
            *(float4*)(b + 4) = *(const float4*)(&Bs[kk][tx * 8 + 4]);
#pragma unroll
            for (int i = 0; i < 8; i++)
#pragma unroll
                for (int j = 0; j < 8; j++)
                    acc[i][j] += a[i] * b[j];
        }
        __syncthreads();
    }

    const int row0 = blockIdx.y * 128 + ty * 8;
    const int col0 = blockIdx.x * 128 + tx * 8;
    float bz[8];
    *(float4*)(bz)     = *(const float4*)(bias + col0);
    *(float4*)(bz + 4) = *(const float4*)(bias + col0 + 4);
#pragma unroll
    for (int i = 0; i < 8; i++) {
        float4 r0, r1;
        r0.x = acc[i][0] + bz[0]; r0.y = acc[i][1] + bz[1];
        r0.z = acc[i][2] + bz[2]; r0.w = acc[i][3] + bz[3];
        r1.x = acc[i][4] + bz[4]; r1.y = acc[i][5] + bz[5];
        r1.z = acc[i][6] + bz[6]; r1.w = acc[i][7] + bz[7];
        float* cp = C + (size_t)(row0 + i) * N + col0;
        *(float4*)cp = r0;
        *(float4*)(cp + 4) = r1;
    }
}

// Fused per-(b,h) attention: 64-query tile per block, online softmax over 16
// key tiles of 64. xw computed once per query tile; scores never hit HBM.
__global__ void __launch_bounds__(256) attn_fused(
    const float* __restrict__ x, const float* __restrict__ watt,
    const float* __restrict__ bias, const float* __restrict__ vx,
    float* __restrict__ outp)
{
    __shared__ float XWs[4096];   // XW^T (e-major, swizzled): persists whole block
    __shared__ float Ss[4096];    // phase0: Xq^T (swz); then scores/probs [q][k]
    __shared__ float Abuf[4096];  // W -> Xk^T (swz) -> alpha[64] -> V [k][d]

    const int tid  = threadIdx.x;
    const int tx   = tid & 15;
    const int ty   = tid >> 4;
    const int lane = tid & 31;
    const int wrp  = tid >> 5;

    const int qb = blockIdx.x;      // 0..15
    const int bh = blockIdx.y;      // 0..255
    const int b  = bh >> 4;
    const int h  = bh & 15;
    const int q0 = qb * 64;

    const float* xb      = x  + (size_t)b * Pp * Ee + h * Dh;
    const float* vb      = vx + (size_t)b * Pp * Ee + h * Dh;
    const float* bh_bias = bias + (size_t)h * Pp * Pp;

    // Phase 0: W[h] -> Abuf (natural [d][e]); Xq -> Ss transposed as Xqs[d][q]
    {
        const float4* Wp4 = (const float4*)(watt + (size_t)h * Dh * Dh);
        float4* Ab4 = (float4*)Abuf;
#pragma unroll
        for (int r = 0; r < 4; r++) {
            int f = tid + r * 256;
            Ab4[f] = Wp4[f];
            int q = f >> 4, dc = f & 15;
            float4 v = *(const float4*)(xb + (size_t)(q0 + q) * Ee + dc * 4);
            Ss[swz(dc * 4 + 0, q)] = v.x;
            Ss[swz(dc * 4 + 1, q)] = v.y;
            Ss[swz(dc * 4 + 2, q)] = v.z;
            Ss[swz(dc * 4 + 3, q)] = v.w;
        }
    }
    __syncthreads();

    // Phase 1: XW[q][e] = sum_d Xq[q][d]*W[d][e], scaled by 1/sqrt(64),
    // stored transposed (e-major) into XWs for the scores GEMM.
    {
        float accv[4][4];
#pragma unroll
        for (int i = 0; i < 4; i++)
#pragma unroll
            for (int j = 0; j < 4; j++) accv[i][j] = 0.f;
#pragma unroll 16
        for (int d = 0; d < 64; d++) {
            float xq[4], w[4];
            *(float4*)xq = *(const float4*)(&Ss[swz(d, ty * 4)]);
            *(float4*)w  = *(const float4*)(&Abuf[d * 64 + tx * 4]);
#pragma unroll
            for (int i = 0; i < 4; i++)
#pragma unroll
                for (int j = 0; j < 4; j++)
                    accv[i][j] += xq[i] * w[j];
        }
        __syncthreads();  // Xqs/W reads done before Ss/Abuf are reused
#pragma unroll
        for (int i = 0; i < 4; i++)
#pragma unroll
            for (int j = 0; j < 4; j++)
                XWs[swz(tx * 4 + j, ty * 4 + i)] = accv[i][j] * 0.125f;
    }
    __syncthreads();

    float o[4][4];
#pragma unroll
    for (int i = 0; i < 4; i++)
#pragma unroll
        for (int j = 0; j < 4; j++) o[i][j] = 0.f;
    float mreg[8], lreg[8];  // warp `wrp` owns softmax rows wrp*8 .. wrp*8+7
#pragma unroll
    for (int r = 0; r < 8; r++) { mreg[r] = -INFINITY; lreg[r] = 0.f; }

    for (int kb = 0; kb < 16; kb++) {
        const int k0 = kb * 64;

        // Xk -> Abuf transposed as Xks[e][k] (swizzled)
#pragma unroll
        for (int r = 0; r < 4; r++) {
            int f = tid + r * 256;
            int k = f >> 4, dc = f & 15;
            float4 v = *(const float4*)(xb + (size_t)(k0 + k) * Ee + dc * 4);
            Abuf[swz(dc * 4 + 0, k)] = v.x;
            Abuf[swz(dc * 4 + 1, k)] = v.y;
            Abuf[swz(dc * 4 + 2, k)] = v.z;
            Abuf[swz(dc * 4 + 3, k)] = v.w;
        }
        __syncthreads();

        // Scores tile S[q][k] = XW[q][:] . Xk[k][:]
        float s[4][4];
#pragma unroll
        for (int i = 0; i < 4; i++)
#pragma unroll
            for (int j = 0; j < 4; j++) s[i][j] = 0.f;
#pragma unroll 16
        for (int e = 0; e < 64; e++) {
            float xw[4], xk[4];
            *(float4*)xw = *(const float4*)(&XWs[swz(e, ty * 4)]);
            *(float4*)xk = *(const float4*)(&Abuf[swz(e, tx * 4)]);
#pragma unroll
            for (int i = 0; i < 4; i++)
#pragma unroll
                for (int j = 0; j < 4; j++)
                    s[i][j] += xw[i] * xk[j];
        }
        // + bias, store to Ss[q][k]
        const float* bp = bh_bias + (size_t)(q0 + ty * 4) * Pp + k0 + tx * 4;
#pragma unroll
        for (int i = 0; i < 4; i++) {
            float4 bv = *(const float4*)(bp + (size_t)i * Pp);
            float4 sv;
            sv.x = s[i][0] + bv.x; sv.y = s[i][1] + bv.y;
            sv.z = s[i][2] + bv.z; sv.w = s[i][3] + bv.w;
            *(float4*)(&Ss[(ty * 4 + i) * 64 + tx * 4]) = sv;
        }
        __syncthreads();

        // Online softmax; probs written back in place; alpha -> Abuf[0..63]
#pragma unroll
        for (int r = 0; r < 8; r++) {
            const int q = wrp * 8 + r;
            float* row = &Ss[q * 64];
            float v0 = row[lane];
            float v1 = row[lane + 32];
            float mx = fmaxf(v0, v1);
#pragma unroll
            for (int off = 16; off > 0; off >>= 1)
                mx = fmaxf(mx, __shfl_xor_sync(0xffffffffu, mx, off));
            float mnew = fmaxf(mreg[r], mx);
            float aa = __expf(mreg[r] - mnew);
            float p0 = __expf(v0 - mnew);
            float p1 = __expf(v1 - mnew);
            float ps = p0 + p1;
#pragma unroll
            for (int off = 16; off > 0; off >>= 1)
                ps += __shfl_xor_sync(0xffffffffu, ps, off);
            lreg[r] = lreg[r] * aa + ps;
            mreg[r] = mnew;
            row[lane]      = p0;
            row[lane + 32] = p1;
            if (lane == 0) Abuf[q] = aa;  // Xks row e=0 is dead now
        }
        __syncthreads();

        // Rescale accumulators by alpha
        float aq[4];
#pragma unroll
        for (int i = 0; i < 4; i++) aq[i] = Abuf[ty * 4 + i];
#pragma unroll
        for (int i = 0; i < 4; i++)
#pragma unroll
            for (int j = 0; j < 4; j++) o[i][j] *= aq[i];
        __syncthreads();  // all alpha reads done before V overwrites Abuf

        // V tile -> Abuf natural [k][d]
        {
            float4* Ab4 = (float4*)Abuf;
#pragma unroll
            for (int r = 0; r < 4; r++) {
                int f = tid + r * 256;
                int k = f >> 4, dc = f & 15;
                Ab4[f] = *(const float4*)(vb + (size_t)(k0 + k) * Ee + dc * 4);
            }
        }
        __syncthreads();

        // O += P @ V  (p scalar-broadcast by ty, v float4 by tx)
#pragma unroll 16
        for (int kk = 0; kk < 64; kk++) {
            float v[4];
            *(float4*)v = *(const float4*)(&Abuf[kk * 64 + tx * 4]);
            float p0 = Ss[(ty * 4 + 0) * 64 + kk];
            float p1 = Ss[(ty * 4 + 1) * 64 + kk];
            float p2 = Ss[(ty * 4 + 2) * 64 + kk];
            float p3 = Ss[(ty * 4 + 3) * 64 + kk];
#pragma unroll
            for (int j = 0; j < 4; j++) {
                o[0][j] += p0 * v[j];
                o[1][j] += p1 * v[j];
                o[2][j] += p2 * v[j];
                o[3][j] += p3 * v[j];
            }
        }
        __syncthreads();
    }

    // Publish final row sums, normalize, write out
    if (lane == 0) {
#pragma unroll
        for (int r = 0; r < 8; r++) Abuf[wrp * 8 + r] = lreg[r];
    }
    __syncthreads();
    float* ob = outp + (size_t)b * Pp * Ee + h * Dh;
#pragma unroll
    for (int i = 0; i < 4; i++) {
        float linv = 1.0f / Abuf[ty * 4 + i];
        float4 w;
        w.x = o[i][0] * linv; w.y = o[i][1] * linv;
        w.z = o[i][2] * linv; w.w = o[i][3] * linv;
        *(float4*)(ob + (size_t)(q0 + ty * 4 + i) * Ee + tx * 4) = w;
    }
}

extern "C" void kernel_launch(void* const* d_in, const int* in_sizes, int n_in,
                              void* d_out, int out_size) {
    const float* x     = (const float*)d_in[0];
    const float* watt  = (const float*)d_in[1];
    const float* abias = (const float*)d_in[2];
    const float* wv_w  = (const float*)d_in[3];
    const float* wv_b  = (const float*)d_in[4];
    const float* out_w = (const float*)d_in[5];
    const float* out_b = (const float*)d_in[6];
    float* outp = (float*)d_out;

    float *vx = nullptr, *att = nullptr;
    cudaGetSymbolAddress((void**)&vx, g_vx);
    cudaGetSymbolAddress((void**)&att, g_att);

    dim3 gg(Ee / 128, (Bb * Pp) / 128);  // (8, 128)

    // 1) vx = x @ wv_w^T + wv_b
    gemm_nt_bias<<<gg, 256>>>(x, wv_w, wv_b, vx, Bb * Pp, Ee, Ee);
    // 2) fused bilinear attention per (b, h), 64-query tiles
    attn_fused<<<dim3(Pp / 64, Bb * Hh), 256>>>(x, watt, abias, vx, att);
    // 3) out = att @ out_w^T + out_b
    gemm_nt_bias<<<gg, 256>>>(att, out_w, out_b, outp, Bb * Pp, Ee, Ee);
}

// round 2
// speedup vs baseline: 1.4092x; 1.4092x over previous
#include <cuda_runtime.h>
#include <math.h>
#include <stdint.h>

#define Bb 16
#define Pp 1024
#define Ee 1024
#define Hh 16
#define Dh 64

// 64 MB scratch each — device globals (allocation-free per harness rules)
__device__ float g_vx[(size_t)Bb * Pp * Ee];
__device__ float g_att[(size_t)Bb * Pp * Ee];

__device__ __forceinline__ uint32_t f2tf(float f) {
    uint32_t u;
    asm("cvt.rna.tf32.f32 %0, %1;" : "=r"(u) : "f"(f));
    return u;
}

#define MMA_TF32(c, a, b)                                              \
    asm volatile(                                                      \
        "mma.sync.aligned.m16n8k8.row.col.f32.tf32.tf32.f32 "          \
        "{%0,%1,%2,%3}, {%4,%5,%6,%7}, {%8,%9}, {%0,%1,%2,%3};"        \
        : "+f"((c)[0]), "+f"((c)[1]), "+f"((c)[2]), "+f"((c)[3])       \
        : "r"((a)[0]), "r"((a)[1]), "r"((a)[2]), "r"((a)[3]),          \
          "r"((b)[0]), "r"((b)[1]))

// C[M,N] = A[M,K] @ B[N,K]^T + bias[N], tf32 tensor cores.
// Block tile 128x128x16; 8 warps as 2(m) x 4(n), each warp 64x32.
// smem stride 20 floats -> conflict-free m16n8k8 fragment LDS.
__global__ void __launch_bounds__(256) gemm_tf32_nt_bias(
    const float* __restrict__ A, const float* __restrict__ Bw,
    const float* __restrict__ bias, float* __restrict__ C,
    int M, int N, int K)
{
    __shared__ uint32_t As[128 * 20];
    __shared__ uint32_t Bs[128 * 20];

    const int tid  = threadIdx.x;
    const int lane = tid & 31;
    const int wid  = tid >> 5;
    const int wm   = wid >> 2;       // 0..1
    const int wn   = wid & 3;        // 0..3
    const int grp  = lane >> 2;      // 0..7
    const int thr  = lane & 3;       // 0..3

    const int rowA0 = blockIdx.y * 128;
    const int colB0 = blockIdx.x * 128;

    // Per-thread gmem tile slots: 2 float4 of A, 2 of B per K-step of 16
    const int i0 = tid, i1 = tid + 256;
    const int ar0 = i0 >> 2, ac0 = (i0 & 3) * 4;
    const int ar1 = i1 >> 2, ac1 = (i1 & 3) * 4;

    const float* Ap0 = A  + (size_t)(rowA0 + ar0) * K + ac0;
    const float* Ap1 = A  + (size_t)(rowA0 + ar1) * K + ac1;
    const float* Bp0 = Bw + (size_t)(colB0 + ar0) * K + ac0;
    const float* Bp1 = Bw + (size_t)(colB0 + ar1) * K + ac1;

    float acc[4][4][4];
#pragma unroll
    for (int mt = 0; mt < 4; mt++)
#pragma unroll
        for (int nt = 0; nt < 4; nt++)
#pragma unroll
            for (int r = 0; r < 4; r++) acc[mt][nt][r] = 0.f;

    float4 ra0, ra1, rb0, rb1;

#define LDG_TILE(k0)                         \
    do {                                     \
        ra0 = *(const float4*)(Ap0 + (k0));  \
        ra1 = *(const float4*)(Ap1 + (k0));  \
        rb0 = *(const float4*)(Bp0 + (k0));  \
        rb1 = *(const float4*)(Bp1 + (k0));  \
    } while (0)

#define STS_TILE()                                                        \
    do {                                                                  \
        uint4 t;                                                          \
        t.x = f2tf(ra0.x); t.y = f2tf(ra0.y);                             \
        t.z = f2tf(ra0.z); t.w = f2tf(ra0.w);                             \
        *(uint4*)(&As[ar0 * 20 + ac0]) = t;                               \
        t.x = f2tf(ra1.x); t.y = f2tf(ra1.y);                             \
        t.z = f2tf(ra1.z); t.w = f2tf(ra1.w);                             \
        *(uint4*)(&As[ar1 * 20 + ac1]) = t;                               \
        t.x = f2tf(rb0.x); t.y = f2tf(rb0.y);                             \
        t.z = f2tf(rb0.z); t.w = f2tf(rb0.w);                             \
        *(uint4*)(&Bs[ar0 * 20 + ac0]) = t;                               \
        t.x = f2tf(rb1.x); t.y = f2tf(rb1.y);                             \
        t.z = f2tf(rb1.z); t.w = f2tf(rb1.w);                             \
        *(uint4*)(&Bs[ar1 * 20 + ac1]) = t;                               \
    } while (0)

#define COMPUTE_TILE()                                                    \
    do {                                                                  \
        _Pragma("unroll")                                                 \
        for (int kk = 0; kk < 16; kk += 8) {                              \
            uint32_t af[4][4], bf[4][2];                                  \
            _Pragma("unroll")                                             \
            for (int mt = 0; mt < 4; mt++) {                              \
                int base = (wm * 64 + mt * 16 + grp) * 20 + kk + thr;     \
                af[mt][0] = As[base];                                     \
                af[mt][1] = As[base + 160];                               \
                af[mt][2] = As[base + 4];                                 \
                af[mt][3] = As[base + 164];                               \
            }                                                             \
            _Pragma("unroll")                                             \
            for (int nt = 0; nt < 4; nt++) {                              \
                int bb = (wn * 32 + nt * 8 + grp) * 20 + kk + thr;        \
                bf[nt][0] = Bs[bb];                                       \
                bf[nt][1] = Bs[bb + 4];                                   \
            }                                                             \
            _Pragma("unroll")                                             \
            for (int mt = 0; mt < 4; mt++)                                \
                _Pragma("unroll")                                         \
                for (int nt = 0; nt < 4; nt++)                            \
                    MMA_TF32(acc[mt][nt], af[mt], bf[nt]);                \
        }                                                                 \
    } while (0)

    LDG_TILE(0);
    STS_TILE();
    __syncthreads();

    for (int k0 = 16; k0 < K; k0 += 16) {
        LDG_TILE(k0);       // prefetch next tile into registers
        COMPUTE_TILE();     // compute on current smem tile
        __syncthreads();
        STS_TILE();
        __syncthreads();
    }
    COMPUTE_TILE();

    // Epilogue: bias add, m16n8 C-fragment layout
#pragma unroll
    for (int mt = 0; mt < 4; mt++) {
        const int row = rowA0 + wm * 64 + mt * 16 + grp;
#pragma unroll
        for (int nt = 0; nt < 4; nt++) {
            const int col = colB0 + wn * 32 + nt * 8 + thr * 2;
            float2 bz = *(const float2*)(bias + col);
            float2 v;
            v.x = acc[mt][nt][0] + bz.x;
            v.y = acc[mt][nt][1] + bz.y;
            *(float2*)(C + (size_t)row * N + col) = v;
            v.x = acc[mt][nt][2] + bz.x;
            v.y = acc[mt][nt][3] + bz.y;
            *(float2*)(C + (size_t)(row + 8) * N + col) = v;
        }
    }
#undef LDG_TILE
#undef STS_TILE
#undef COMPUTE_TILE
}

// XOR swizzle on 4-float chunks within a 64-float row: keeps float4 reads
// conflict-free while reducing transposed scalar stores from 16-way to 2-way.
__device__ __forceinline__ int swz(int row, int col) {
    return (row << 6) + ((((col >> 2) ^ (row >> 2)) & 15) << 2) + (col & 3);
}

// Fused per-(b,h) attention: 64-query tile per block, online softmax over 16
// key tiles of 64. xw computed once per query tile; scores never hit HBM.
__global__ void __launch_bounds__(256) attn_fused(
    const float* __restrict__ x, const float* __restrict__ watt,
    const float* __restrict__ bias, const float* __restrict__ vx,
    float* __restrict__ outp)
{
    __shared__ float XWs[4096];   // XW^T (e-major, swizzled): persists whole block
    __shared__ float Ss[4096];    // phase0: Xq^T (swz); then scores/probs [q][k]
    __shared__ float Abuf[4096];  // W -> Xk^T (swz) -> alpha[64] -> V [k][d]

    const int tid  = threadIdx.x;
    const int tx   = tid & 15;
    const int ty   = tid >> 4;
    const int lane = tid & 31;
    const int wrp  = tid >> 5;

    const int qb = blockIdx.x;      // 0..15
    const int bh = blockIdx.y;      // 0..255
    const int b  = bh >> 4;
    const int h  = bh & 15;
    const int q0 = qb * 64;

    const float* xb      = x  + (size_t)b * Pp * Ee + h * Dh;
    const float* vb      = vx + (size_t)b * Pp * Ee + h * Dh;
    const float* bh_bias = bias + (size_t)h * Pp * Pp;

    // Phase 0: W[h] -> Abuf (natural [d][e]); Xq -> Ss transposed as Xqs[d][q]
    {
        const float4* Wp4 = (const float4*)(watt + (size_t)h * Dh * Dh);
        float4* Ab4 = (float4*)Abuf;
#pragma unroll
        for (int r = 0; r < 4; r++) {
            int f = tid + r * 256;
            Ab4[f] = Wp4[f];
            int q = f >> 4, dc = f & 15;
            float4 v = *(const float4*)(xb + (size_t)(q0 + q) * Ee + dc * 4);
            Ss[swz(dc * 4 + 0, q)] = v.x;
            Ss[swz(dc * 4 + 1, q)] = v.y;
            Ss[swz(dc * 4 + 2, q)] = v.z;
            Ss[swz(dc * 4 + 3, q)] = v.w;
        }
    }
    __syncthreads();

    // Phase 1: XW[q][e] = sum_d Xq[q][d]*W[d][e], scaled by 1/sqrt(64),
    // stored transposed (e-major) into XWs for the scores GEMM.
    {
        float accv[4][4];
#pragma unroll
        for (int i = 0; i < 4; i++)
#pragma unroll
            for (int j = 0; j < 4; j++) accv[i][j] = 0.f;
#pragma unroll 16
        for (int d = 0; d < 64; d++) {
            float xq[4], w[4];
            *(float4*)xq = *(const float4*)(&Ss[swz(d, ty * 4)]);
            *(float4*)w  = *(const float4*)(&Abuf[d * 64 + tx * 4]);
#pragma unroll
            for (int i = 0; i < 4; i++)
#pragma unroll
                for (int j = 0; j < 4; j++)
                    accv[i][j] += xq[i] * w[j];
        }
        __syncthreads();  // Xqs/W reads done before Ss/Abuf are reused
#pragma unroll
        for (int i = 0; i < 4; i++)
#pragma unroll
            for (int j = 0; j < 4; j++)
                XWs[swz(tx * 4 + j, ty * 4 + i)] = accv[i][j] * 0.125f;
    }
    __syncthreads();

    float o[4][4];
#pragma unroll
    for (int i = 0; i < 4; i++)
#pragma unroll
        for (int j = 0; j < 4; j++) o[i][j] = 0.f;
    float mreg[8], lreg[8];  // warp `wrp` owns softmax rows wrp*8 .. wrp*8+7
#pragma unroll
    for (int r = 0; r < 8; r++) { mreg[r] = -INFINITY; lreg[r] = 0.f; }

    for (int kb = 0; kb < 16; kb++) {
        const int k0 = kb * 64;

        // Xk -> Abuf transposed as Xks[e][k] (swizzled)
#pragma unroll
        for (int r = 0; r < 4; r++) {
            int f = tid + r * 256;
            int k = f >> 4, dc = f & 15;
            float4 v = *(const float4*)(xb + (size_t)(k0 + k) * Ee + dc * 4);
            Abuf[swz(dc * 4 + 0, k)] = v.x;
            Abuf[swz(dc * 4 + 1, k)] = v.y;
            Abuf[swz(dc * 4 + 2, k)] = v.z;
            Abuf[swz(dc * 4 + 3, k)] = v.w;
        }
        __syncthreads();

        // Scores tile S[q][k] = XW[q][:] . Xk[k][:]
        float s[4][4];
#pragma unroll
        for (int i = 0; i < 4; i++)
#pragma unroll
            for (int j = 0; j < 4; j++) s[i][j] = 0.f;
#pragma unroll 16
        for (int e = 0; e < 64; e++) {
            float xw[4], xk[4];
            *(float4*)xw = *(const float4*)(&XWs[swz(e, ty * 4)]);
            *(float4*)xk = *(const float4*)(&Abuf[swz(e, tx * 4)]);
#pragma unroll
            for (int i = 0; i < 4; i++)
#pragma unroll
                for (int j = 0; j < 4; j++)
                    s[i][j] += xw[i] * xk[j];
        }
        // + bias, store to Ss[q][k]
        const float* bp = bh_bias + (size_t)(q0 + ty * 4) * Pp + k0 + tx * 4;
#pragma unroll
        for (int i = 0; i < 4; i++) {
            float4 bv = *(const float4*)(bp + (size_t)i * Pp);
            float4 sv;
            sv.x = s[i][0] + bv.x; sv.y = s[i][1] + bv.y;
            sv.z = s[i][2] + bv.z; sv.w = s[i][3] + bv.w;
            *(float4*)(&Ss[(ty * 4 + i) * 64 + tx * 4]) = sv;
        }
        __syncthreads();

        // Online softmax; probs written back in place; alpha -> Abuf[0..63]
#pragma unroll
        for (int r = 0; r < 8; r++) {
            const int q = wrp * 8 + r;
            float* row = &Ss[q * 64];
            float v0 = row[lane];
            float v1 = row[lane + 32];
            float mx = fmaxf(v0, v1);
#pragma unroll
            for (int off = 16; off > 0; off >>= 1)
                mx = fmaxf(mx, __shfl_xor_sync(0xffffffffu, mx, off));
            float mnew = fmaxf(mreg[r], mx);
            float aa = __expf(mreg[r] - mnew);
            float p0 = __expf(v0 - mnew);
            float p1 = __expf(v1 - mnew);
            float ps = p0 + p1;
#pragma unroll
            for (int off = 16; off > 0; off >>= 1)
                ps += __shfl_xor_sync(0xffffffffu, ps, off);
            lreg[r] = lreg[r] * aa + ps;
            mreg[r] = mnew;
            row[lane]      = p0;
            row[lane + 32] = p1;
            if (lane == 0) Abuf[q] = aa;  // Xks row e=0 is dead now
        }
        __syncthreads();

        // Rescale accumulators by alpha
        float aq[4];
#pragma unroll
        for (int i = 0; i < 4; i++) aq[i] = Abuf[ty * 4 + i];
#pragma unroll
        for (int i = 0; i < 4; i++)
#pragma unroll
            for (int j = 0; j < 4; j++) o[i][j] *= aq[i];
        __syncthreads();  // all alpha reads done before V overwrites Abuf

        // V tile -> Abuf natural [k][d]
        {
            float4* Ab4 = (float4*)Abuf;
#pragma unroll
            for (int r = 0; r < 4; r++) {
                int f = tid + r * 256;
                int k = f >> 4, dc = f & 15;
                Ab4[f] = *(const float4*)(vb + (size_t)(k0 + k) * Ee + dc * 4);
            }
        }
        __syncthreads();

        // O += P @ V  (p scalar-broadcast by ty, v float4 by tx)
#pragma unroll 16
        for (int kk = 0; kk < 64; kk++) {
            float v[4];
            *(float4*)v = *(const float4*)(&Abuf[kk * 64 + tx * 4]);
            float p0 = Ss[(ty * 4 + 0) * 64 + kk];
            float p1 = Ss[(ty * 4 + 1) * 64 + kk];
            float p2 = Ss[(ty * 4 + 2) * 64 + kk];
            float p3 = Ss[(ty * 4 + 3) * 64 + kk];
#pragma unroll
            for (int j = 0; j < 4; j++) {
                o[0][j] += p0 * v[j];
                o[1][j] += p1 * v[j];
                o[2][j] += p2 * v[j];
                o[3][j] += p3 * v[j];
            }
        }
        __syncthreads();
    }

    // Publish final row sums, normalize, write out
    if (lane == 0) {
#pragma unroll
        for (int r = 0; r < 8; r++) Abuf[wrp * 8 + r] = lreg[r];
    }
    __syncthreads();
    float* ob = outp + (size_t)b * Pp * Ee + h * Dh;
#pragma unroll
    for (int i = 0; i < 4; i++) {
        float linv = 1.0f / Abuf[ty * 4 + i];
        float4 w;
        w.x = o[i][0] * linv; w.y = o[i][1] * linv;
        w.z = o[i][2] * linv; w.w = o[i][3] * linv;
        *(float4*)(ob + (size_t)(q0 + ty * 4 + i) * Ee + tx * 4) = w;
    }
}

extern "C" void kernel_launch(void* const* d_in, const int* in_sizes, int n_in,
                              void* d_out, int out_size) {
    const float* x     = (const float*)d_in[0];
    const float* watt  = (const float*)d_in[1];
    const float* abias = (const float*)d_in[2];
    const float* wv_w  = (const float*)d_in[3];
    const float* wv_b  = (const float*)d_in[4];
    const float* out_w = (const float*)d_in[5];
    const float* out_b = (const float*)d_in[6];
    float* outp = (float*)d_out;

    float *vx = nullptr, *att = nullptr;
    cudaGetSymbolAddress((void**)&vx, g_vx);
    cudaGetSymbolAddress((void**)&att, g_att);

    dim3 gg(Ee / 128, (Bb * Pp) / 128);  // (8, 128)

    // 1) vx = x @ wv_w^T + wv_b  (tf32 tensor cores)
    gemm_tf32_nt_bias<<<gg, 256>>>(x, wv_w, wv_b, vx, Bb * Pp, Ee, Ee);
    // 2) fused bilinear attention per (b, h), 64-query tiles
    attn_fused<<<dim3(Pp / 64, Bb * Hh), 256>>>(x, watt, abias, vx, att);
    // 3) out = att @ out_w^T + out_b  (tf32 tensor cores)
    gemm_tf32_nt_bias<<<gg, 256>>>(att, out_w, out_b, outp, Bb * Pp, Ee, Ee);
}

// round 3
// speedup vs baseline: 3.1133x; 2.2092x over previous
#include <cuda_runtime.h>
#include <math.h>
#include <stdint.h>

#define Bb 16
#define Pp 1024
#define Ee 1024
#define Hh 16
#define Dh 64

// Device-global scratch (allocation-free per harness rules)
__device__ float g_vxT[(size_t)Bb * Hh * Dh * Pp];  // vx transposed per head: [b][h][d][p]
__device__ float g_att[(size_t)Bb * Pp * Ee];

__device__ __forceinline__ uint32_t f2tf(float f) {
    uint32_t u;
    asm("cvt.rna.tf32.f32 %0, %1;" : "=r"(u) : "f"(f));
    return u;
}

#define MMA_TF32(c, a, b)                                              \
    asm volatile(                                                      \
        "mma.sync.aligned.m16n8k8.row.col.f32.tf32.tf32.f32 "          \
        "{%0,%1,%2,%3}, {%4,%5,%6,%7}, {%8,%9}, {%0,%1,%2,%3};"        \
        : "+f"((c)[0]), "+f"((c)[1]), "+f"((c)[2]), "+f"((c)[3])       \
        : "r"((a)[0]), "r"((a)[1]), "r"((a)[2]), "r"((a)[3]),          \
          "r"((b)[0]), "r"((b)[1]))

// C[M,N] = A[M,K] @ B[N,K]^T + bias[N], tf32, double-buffered smem.
// TRANSV=true: write C transposed per 64-wide head: dst[b][h][d][p].
template <bool TRANSV>
__global__ void __launch_bounds__(256) gemm_tf32(
    const float* __restrict__ A, const float* __restrict__ Bw,
    const float* __restrict__ bias, float* __restrict__ C,
    int M, int N, int K)
{
    __shared__ uint32_t As[2][128 * 20];
    __shared__ uint32_t Bs[2][128 * 20];

    const int tid  = threadIdx.x;
    const int lane = tid & 31;
    const int wid  = tid >> 5;
    const int wm   = wid >> 2;
    const int wn   = wid & 3;
    const int grp  = lane >> 2;
    const int thr  = lane & 3;

    const int rowA0 = blockIdx.y * 128;
    const int colB0 = blockIdx.x * 128;

    const int i0 = tid, i1 = tid + 256;
    const int ar0 = i0 >> 2, ac0 = (i0 & 3) * 4;
    const int ar1 = i1 >> 2, ac1 = (i1 & 3) * 4;

    const float* Ap0 = A  + (size_t)(rowA0 + ar0) * K + ac0;
    const float* Ap1 = A  + (size_t)(rowA0 + ar1) * K + ac1;
    const float* Bp0 = Bw + (size_t)(colB0 + ar0) * K + ac0;
    const float* Bp1 = Bw + (size_t)(colB0 + ar1) * K + ac1;

    float acc[4][4][4];
#pragma unroll
    for (int mt = 0; mt < 4; mt++)
#pragma unroll
        for (int nt = 0; nt < 4; nt++)
#pragma unroll
            for (int r = 0; r < 4; r++) acc[mt][nt][r] = 0.f;

    float4 ra0, ra1, rb0, rb1;

#define LDG_TILE(k0)                         \
    do {                                     \
        ra0 = *(const float4*)(Ap0 + (k0));  \
        ra1 = *(const float4*)(Ap1 + (k0));  \
        rb0 = *(const float4*)(Bp0 + (k0));  \
        rb1 = *(const float4*)(Bp1 + (k0));  \
    } while (0)

#define STS_TILE(bi)                                                      \
    do {                                                                  \
        uint4 t;                                                          \
        t.x = f2tf(ra0.x); t.y = f2tf(ra0.y);                             \
        t.z = f2tf(ra0.z); t.w = f2tf(ra0.w);                             \
        *(uint4*)(&As[bi][ar0 * 20 + ac0]) = t;                           \
        t.x = f2tf(ra1.x); t.y = f2tf(ra1.y);                             \
        t.z = f2tf(ra1.z); t.w = f2tf(ra1.w);                             \
        *(uint4*)(&As[bi][ar1 * 20 + ac1]) = t;                           \
        t.x = f2tf(rb0.x); t.y = f2tf(rb0.y);                             \
        t.z = f2tf(rb0.z); t.w = f2tf(rb0.w);                             \
        *(uint4*)(&Bs[bi][ar0 * 20 + ac0]) = t;                           \
        t.x = f2tf(rb1.x); t.y = f2tf(rb1.y);                             \
        t.z = f2tf(rb1.z); t.w = f2tf(rb1.w);                             \
        *(uint4*)(&Bs[bi][ar1 * 20 + ac1]) = t;                           \
    } while (0)

#define COMPUTE_TILE(bi)                                                  \
    do {                                                                  \
        _Pragma("unroll")                                                 \
        for (int kk = 0; kk < 16; kk += 8) {                              \
            uint32_t af[4][4], bf[4][2];                                  \
            _Pragma("unroll")                                             \
            for (int mt = 0; mt < 4; mt++) {                              \
                int base = (wm * 64 + mt * 16 + grp) * 20 + kk + thr;     \
                af[mt][0] = As[bi][base];                                 \
                af[mt][1] = As[bi][base + 160];                           \
                af[mt][2] = As[bi][base + 4];                             \
                af[mt][3] = As[bi][base + 164];                           \
            }                                                             \
            _Pragma("unroll")                                             \
            for (int nt = 0; nt < 4; nt++) {                              \
                int bb = (wn * 32 + nt * 8 + grp) * 20 + kk + thr;        \
                bf[nt][0] = Bs[bi][bb];                                   \
                bf[nt][1] = Bs[bi][bb + 4];                               \
            }                                                             \
            _Pragma("unroll")                                             \
            for (int mt = 0; mt < 4; mt++)                                \
                _Pragma("unroll")                                         \
                for (int nt = 0; nt < 4; nt++)                            \
                    MMA_TF32(acc[mt][nt], af[mt], bf[nt]);                \
        }                                                                 \
    } while (0)

    LDG_TILE(0);
    STS_TILE(0);
    __syncthreads();

    int cur = 0;
    for (int k0 = 16; k0 < K; k0 += 16) {
        LDG_TILE(k0);
        COMPUTE_TILE(cur);
        STS_TILE(cur ^ 1);
        __syncthreads();
        cur ^= 1;
    }
    COMPUTE_TILE(cur);

#pragma unroll
    for (int mt = 0; mt < 4; mt++) {
        const int row = rowA0 + wm * 64 + mt * 16 + grp;
#pragma unroll
        for (int nt = 0; nt < 4; nt++) {
            const int col = colB0 + wn * 32 + nt * 8 + thr * 2;
            float2 bz = *(const float2*)(bias + col);
            if (!TRANSV) {
                float2 v;
                v.x = acc[mt][nt][0] + bz.x;
                v.y = acc[mt][nt][1] + bz.y;
                *(float2*)(C + (size_t)row * N + col) = v;
                v.x = acc[mt][nt][2] + bz.x;
                v.y = acc[mt][nt][3] + bz.y;
                *(float2*)(C + (size_t)(row + 8) * N + col) = v;
            } else {
                // dst[((b*16+h)*64+d)*1024 + p], h=col/64, d=col%64, b=row/1024, p=row%1024
                const int bx = row >> 10;
                const int p  = row & 1023;
                const size_t d0 = ((size_t)(bx * Hh + (col >> 6)) * Dh + (col & 63)) * Pp;
                const size_t d1 = d0 + Pp;  // col+1 (never crosses head: col is even)
                C[d0 + p]     = acc[mt][nt][0] + bz.x;
                C[d1 + p]     = acc[mt][nt][1] + bz.y;
                C[d0 + p + 8] = acc[mt][nt][2] + bz.x;
                C[d1 + p + 8] = acc[mt][nt][3] + bz.y;
            }
        }
    }
#undef LDG_TILE
#undef STS_TILE
#undef COMPUTE_TILE
}

// Fused bilinear attention, tf32 tensor cores.
// Block: one (b,h), 128 queries. 8 warps x m16. Key tiles of 64.
// Smem rows stride 76 floats (=304B, 16B aligned, conflict-free frag LDS).
#define ST 76
__global__ void __launch_bounds__(256, 2) attn_mma(
    const float* __restrict__ x, const float* __restrict__ watt,
    const float* __restrict__ bias, const float* __restrict__ vxT,
    float* __restrict__ outp)
{
    extern __shared__ uint32_t sm[];
    uint32_t* XWs = sm;                 // [128][ST] tf32 XW (scaled)
    uint32_t* Ps  = sm + 128 * ST;      // [128][ST] Xq then P tiles
    uint32_t* KVs = sm + 2 * 128 * ST;  // [64][ST]  W^T / Xk / V^T tiles

    const int tid  = threadIdx.x;
    const int lane = tid & 31;
    const int wid  = tid >> 5;
    const int grp  = lane >> 2;
    const int thr  = lane & 3;
    const int m0   = wid * 16;

    const int q0 = blockIdx.x * 128;
    const int bh = blockIdx.y;
    const int b  = bh >> 4;
    const int h  = bh & 15;

    const float* xb  = x + (size_t)b * Pp * Ee + h * Dh;
    const float* vtb = vxT + (size_t)bh * Dh * Pp;
    const float* bb  = bias + (size_t)h * Pp * Pp;

    // Phase 0: Xq -> Ps (tf32), W^T -> KVs (tf32)
#pragma unroll
    for (int r = 0; r < 8; r++) {
        int idx = tid + r * 256;
        int q = idx >> 4, c = (idx & 15) * 4;
        float4 v = *(const float4*)(xb + (size_t)(q0 + q) * Ee + c);
        uint4 t;
        t.x = f2tf(v.x); t.y = f2tf(v.y); t.z = f2tf(v.z); t.w = f2tf(v.w);
        *(uint4*)(&Ps[q * ST + c]) = t;
    }
    {
        const float* Wp = watt + (size_t)h * Dh * Dh;
#pragma unroll
        for (int r = 0; r < 4; r++) {
            int idx = tid + r * 256;
            int d = idx >> 4, e = (idx & 15) * 4;
            float4 v = *(const float4*)(Wp + d * Dh + e);
            KVs[(e + 0) * ST + d] = f2tf(v.x);
            KVs[(e + 1) * ST + d] = f2tf(v.y);
            KVs[(e + 2) * ST + d] = f2tf(v.z);
            KVs[(e + 3) * ST + d] = f2tf(v.w);
        }
    }
    __syncthreads();

    // Phase 1: XW = (Xq @ W) / 8 -> XWs
    {
        float c[8][4];
#pragma unroll
        for (int nt = 0; nt < 8; nt++)
#pragma unroll
            for (int r = 0; r < 4; r++) c[nt][r] = 0.f;
#pragma unroll
        for (int kk = 0; kk < 64; kk += 8) {
            uint32_t a[4];
            a[0] = Ps[(m0 + grp) * ST + kk + thr];
            a[1] = Ps[(m0 + grp + 8) * ST + kk + thr];
            a[2] = Ps[(m0 + grp) * ST + kk + 4 + thr];
            a[3] = Ps[(m0 + grp + 8) * ST + kk + 4 + thr];
#pragma unroll
            for (int nt = 0; nt < 8; nt++) {
                uint32_t bf[2];
                bf[0] = KVs[(nt * 8 + grp) * ST + kk + thr];
                bf[1] = KVs[(nt * 8 + grp) * ST + kk + 4 + thr];
                MMA_TF32(c[nt], a, bf);
            }
        }
#pragma unroll
        for (int nt = 0; nt < 8; nt++) {
            XWs[(m0 + grp) * ST + nt * 8 + 2 * thr]         = f2tf(c[nt][0] * 0.125f);
            XWs[(m0 + grp) * ST + nt * 8 + 2 * thr + 1]     = f2tf(c[nt][1] * 0.125f);
            XWs[(m0 + grp + 8) * ST + nt * 8 + 2 * thr]     = f2tf(c[nt][2] * 0.125f);
            XWs[(m0 + grp + 8) * ST + nt * 8 + 2 * thr + 1] = f2tf(c[nt][3] * 0.125f);
        }
    }
    __syncthreads();

    float o[8][4];
#pragma unroll
    for (int dt = 0; dt < 8; dt++)
#pragma unroll
        for (int r = 0; r < 4; r++) o[dt][r] = 0.f;
    float m0r = -INFINITY, m1r = -INFINITY, l0 = 0.f, l1 = 0.f;

    for (int kb = 0; kb < 16; kb++) {
        const int k0 = kb * 64;

        // Xk tile -> KVs
#pragma unroll
        for (int r = 0; r < 4; r++) {
            int idx = tid + r * 256;
            int k = idx >> 4, c = (idx & 15) * 4;
            float4 v = *(const float4*)(xb + (size_t)(k0 + k) * Ee + c);
            uint4 t;
            t.x = f2tf(v.x); t.y = f2tf(v.y); t.z = f2tf(v.z); t.w = f2tf(v.w);
            *(uint4*)(&KVs[k * ST + c]) = t;
        }
        __syncthreads();

        // S = XW @ Xk^T
        float s[8][4];
#pragma unroll
        for (int nt = 0; nt < 8; nt++)
#pragma unroll
            for (int r = 0; r < 4; r++) s[nt][r] = 0.f;
#pragma unroll
        for (int kk = 0; kk < 64; kk += 8) {
            uint32_t a[4];
            a[0] = XWs[(m0 + grp) * ST + kk + thr];
            a[1] = XWs[(m0 + grp + 8) * ST + kk + thr];
            a[2] = XWs[(m0 + grp) * ST + kk + 4 + thr];
            a[3] = XWs[(m0 + grp + 8) * ST + kk + 4 + thr];
#pragma unroll
            for (int nt = 0; nt < 8; nt++) {
                uint32_t bf[2];
                bf[0] = KVs[(nt * 8 + grp) * ST + kk + thr];
                bf[1] = KVs[(nt * 8 + grp) * ST + kk + 4 + thr];
                MMA_TF32(s[nt], a, bf);
            }
        }

        // bias + online softmax (all in registers; quad reductions)
        const float* bp0 = bb + (size_t)(q0 + m0 + grp) * Pp + k0;
        const float* bp1 = bp0 + 8 * Pp;
        float mx0 = -INFINITY, mx1 = -INFINITY;
#pragma unroll
        for (int nt = 0; nt < 8; nt++) {
            float2 bz0 = *(const float2*)(bp0 + nt * 8 + 2 * thr);
            float2 bz1 = *(const float2*)(bp1 + nt * 8 + 2 * thr);
            s[nt][0] += bz0.x; s[nt][1] += bz0.y;
            s[nt][2] += bz1.x; s[nt][3] += bz1.y;
            mx0 = fmaxf(mx0, fmaxf(s[nt][0], s[nt][1]));
            mx1 = fmaxf(mx1, fmaxf(s[nt][2], s[nt][3]));
        }
        mx0 = fmaxf(mx0, __shfl_xor_sync(0xffffffffu, mx0, 1));
        mx0 = fmaxf(mx0, __shfl_xor_sync(0xffffffffu, mx0, 2));
        mx1 = fmaxf(mx1, __shfl_xor_sync(0xffffffffu, mx1, 1));
        mx1 = fmaxf(mx1, __shfl_xor_sync(0xffffffffu, mx1, 2));
        float mn0 = fmaxf(m0r, mx0), mn1 = fmaxf(m1r, mx1);
        float al0 = __expf(m0r - mn0), al1 = __expf(m1r - mn1);
        m0r = mn0; m1r = mn1;
        float ps0 = 0.f, ps1 = 0.f;
#pragma unroll
        for (int nt = 0; nt < 8; nt++) {
            s[nt][0] = __expf(s[nt][0] - mn0);
            s[nt][1] = __expf(s[nt][1] - mn0);
            s[nt][2] = __expf(s[nt][2] - mn1);
            s[nt][3] = __expf(s[nt][3] - mn1);
            ps0 += s[nt][0] + s[nt][1];
            ps1 += s[nt][2] + s[nt][3];
        }
        ps0 += __shfl_xor_sync(0xffffffffu, ps0, 1);
        ps0 += __shfl_xor_sync(0xffffffffu, ps0, 2);
        ps1 += __shfl_xor_sync(0xffffffffu, ps1, 1);
        ps1 += __shfl_xor_sync(0xffffffffu, ps1, 2);
        l0 = l0 * al0 + ps0;
        l1 = l1 * al1 + ps1;
#pragma unroll
        for (int dt = 0; dt < 8; dt++) {
            o[dt][0] *= al0; o[dt][1] *= al0;
            o[dt][2] *= al1; o[dt][3] *= al1;
        }

        // P -> Ps (tf32)
#pragma unroll
        for (int nt = 0; nt < 8; nt++) {
            Ps[(m0 + grp) * ST + nt * 8 + 2 * thr]         = f2tf(s[nt][0]);
            Ps[(m0 + grp) * ST + nt * 8 + 2 * thr + 1]     = f2tf(s[nt][1]);
            Ps[(m0 + grp + 8) * ST + nt * 8 + 2 * thr]     = f2tf(s[nt][2]);
            Ps[(m0 + grp + 8) * ST + nt * 8 + 2 * thr + 1] = f2tf(s[nt][3]);
        }
        __syncthreads();

        // V^T tile -> KVs (natural row loads thanks to vxT layout)
#pragma unroll
        for (int r = 0; r < 4; r++) {
            int idx = tid + r * 256;
            int d = idx >> 4, c = (idx & 15) * 4;
            float4 v = *(const float4*)(vtb + (size_t)d * Pp + k0 + c);
            uint4 t;
            t.x = f2tf(v.x); t.y = f2tf(v.y); t.z = f2tf(v.z); t.w = f2tf(v.w);
            *(uint4*)(&KVs[d * ST + c]) = t;
        }
        __syncthreads();

        // O += P @ V
#pragma unroll
        for (int kk = 0; kk < 64; kk += 8) {
            uint32_t a[4];
            a[0] = Ps[(m0 + grp) * ST + kk + thr];
            a[1] = Ps[(m0 + grp + 8) * ST + kk + thr];
            a[2] = Ps[(m0 + grp) * ST + kk + 4 + thr];
            a[3] = Ps[(m0 + grp + 8) * ST + kk + 4 + thr];
#pragma unroll
            for (int dt = 0; dt < 8; dt++) {
                uint32_t bf[2];
                bf[0] = KVs[(dt * 8 + grp) * ST + kk + thr];
                bf[1] = KVs[(dt * 8 + grp) * ST + kk + 4 + thr];
                MMA_TF32(o[dt], a, bf);
            }
        }
        __syncthreads();
    }

    // Normalize and write out (natural [b][p][e] layout for the out-projection)
    const float li0 = 1.f / l0, li1 = 1.f / l1;
    float* ob = outp + (size_t)b * Pp * Ee + h * Dh;
#pragma unroll
    for (int dt = 0; dt < 8; dt++) {
        float2 v0, v1;
        v0.x = o[dt][0] * li0; v0.y = o[dt][1] * li0;
        v1.x = o[dt][2] * li1; v1.y = o[dt][3] * li1;
        *(float2*)(ob + (size_t)(q0 + m0 + grp) * Ee + dt * 8 + 2 * thr) = v0;
        *(float2*)(ob + (size_t)(q0 + m0 + grp + 8) * Ee + dt * 8 + 2 * thr) = v1;
    }
}

extern "C" void kernel_launch(void* const* d_in, const int* in_sizes, int n_in,
                              void* d_out, int out_size) {
    const float* x     = (const float*)d_in[0];
    const float* watt  = (const float*)d_in[1];
    const float* abias = (const float*)d_in[2];
    const float* wv_w  = (const float*)d_in[3];
    const float* wv_b  = (const float*)d_in[4];
    const float* out_w = (const float*)d_in[5];
    const float* out_b = (const float*)d_in[6];
    float* outp = (float*)d_out;

    float *vxT = nullptr, *att = nullptr;
    cudaGetSymbolAddress((void**)&vxT, g_vxT);
    cudaGetSymbolAddress((void**)&att, g_att);

    const int attn_smem = 2 * 128 * ST * 4 + 64 * ST * 4;  // 97280 B
    cudaFuncSetAttribute(attn_mma, cudaFuncAttributeMaxDynamicSharedMemorySize,
                         attn_smem);

    dim3 gg(Ee / 128, (Bb * Pp) / 128);  // (8, 128)

    // 1) vxT[b][h][d][p] = (x @ wv_w^T + wv_b) transposed per head
    gemm_tf32<true><<<gg, 256>>>(x, wv_w, wv_b, vxT, Bb * Pp, Ee, Ee);
    // 2) fused bilinear attention (tf32 mma), 128-query tiles
    attn_mma<<<dim3(Pp / 128, Bb * Hh), 256, attn_smem>>>(x, watt, abias, vxT, att);
    // 3) out = att @ out_w^T + out_b
    gemm_tf32<false><<<gg, 256>>>(att, out_w, out_b, outp, Bb * Pp, Ee, Ee);
}

// round 4
// speedup vs baseline: 3.3268x; 1.0686x over previous
#include <cuda_runtime.h>
#include <math.h>
#include <stdint.h>

#define Bb 16
#define Pp 1024
#define Ee 1024
#define Hh 16
#define Dh 64

// Device-global scratch (allocation-free per harness rules)
__device__ float g_vxT[(size_t)Bb * Hh * Dh * Pp];  // vx transposed per head: [b][h][d][p]
__device__ float g_att[(size_t)Bb * Pp * Ee];

__device__ __forceinline__ uint32_t f2tf(float f) {
    uint32_t u;
    asm("cvt.rna.tf32.f32 %0, %1;" : "=r"(u) : "f"(f));
    return u;
}

#define MMA_TF32(c, a, b)                                              \
    asm volatile(                                                      \
        "mma.sync.aligned.m16n8k8.row.col.f32.tf32.tf32.f32 "          \
        "{%0,%1,%2,%3}, {%4,%5,%6,%7}, {%8,%9}, {%0,%1,%2,%3};"        \
        : "+f"((c)[0]), "+f"((c)[1]), "+f"((c)[2]), "+f"((c)[3])       \
        : "r"((a)[0]), "r"((a)[1]), "r"((a)[2]), "r"((a)[3]),          \
          "r"((b)[0]), "r"((b)[1]))

// C[M,N] = A[M,K] @ B[N,K]^T + bias[N], tf32, double-buffered smem.
// 128x128 block, 4 warps as 2x2, each warp 64x64 (128 B LDS per MMA).
// TRANSV=true: write C transposed per 64-wide head: dst[b][h][d][p].
template <bool TRANSV>
__global__ void __launch_bounds__(128) gemm_tf32(
    const float* __restrict__ A, const float* __restrict__ Bw,
    const float* __restrict__ bias, float* __restrict__ C,
    int M, int N, int K)
{
    __shared__ uint32_t As[2][128 * 20];
    __shared__ uint32_t Bs[2][128 * 20];

    const int tid  = threadIdx.x;
    const int lane = tid & 31;
    const int wid  = tid >> 5;       // 0..3
    const int wm   = wid >> 1;       // 0..1
    const int wn   = wid & 1;        // 0..1
    const int grp  = lane >> 2;      // 0..7
    const int thr  = lane & 3;       // 0..3

    const int rowA0 = blockIdx.y * 128;
    const int colB0 = blockIdx.x * 128;

    // Per-thread gmem slots: 4 float4 of A + 4 of B per K-step of 16
    int ar[4], ac[4];
#pragma unroll
    for (int r = 0; r < 4; r++) {
        int i = tid + r * 128;
        ar[r] = i >> 2;
        ac[r] = (i & 3) * 4;
    }
    const float *Ap[4], *Bp[4];
#pragma unroll
    for (int r = 0; r < 4; r++) {
        Ap[r] = A  + (size_t)(rowA0 + ar[r]) * K + ac[r];
        Bp[r] = Bw + (size_t)(colB0 + ar[r]) * K + ac[r];
    }

    float acc[4][8][4];
#pragma unroll
    for (int mt = 0; mt < 4; mt++)
#pragma unroll
        for (int nt = 0; nt < 8; nt++)
#pragma unroll
            for (int r = 0; r < 4; r++) acc[mt][nt][r] = 0.f;

    float4 ra[4], rb[4];

#define LDG_TILE(k0)                                   \
    do {                                               \
        _Pragma("unroll")                              \
        for (int r = 0; r < 4; r++) {                  \
            ra[r] = *(const float4*)(Ap[r] + (k0));    \
            rb[r] = *(const float4*)(Bp[r] + (k0));    \
        }                                              \
    } while (0)

#define STS_TILE(bi)                                                      \
    do {                                                                  \
        _Pragma("unroll")                                                 \
        for (int r = 0; r < 4; r++) {                                     \
            uint4 t;                                                      \
            t.x = f2tf(ra[r].x); t.y = f2tf(ra[r].y);                     \
            t.z = f2tf(ra[r].z); t.w = f2tf(ra[r].w);                     \
            *(uint4*)(&As[bi][ar[r] * 20 + ac[r]]) = t;                   \
            t.x = f2tf(rb[r].x); t.y = f2tf(rb[r].y);                     \
            t.z = f2tf(rb[r].z); t.w = f2tf(rb[r].w);                     \
            *(uint4*)(&Bs[bi][ar[r] * 20 + ac[r]]) = t;                   \
        }                                                                 \
    } while (0)

#define COMPUTE_TILE(bi)                                                  \
    do {                                                                  \
        _Pragma("unroll")                                                 \
        for (int kk = 0; kk < 16; kk += 8) {                              \
            uint32_t af[4][4];                                            \
            _Pragma("unroll")                                             \
            for (int mt = 0; mt < 4; mt++) {                              \
                int base = (wm * 64 + mt * 16 + grp) * 20 + kk + thr;     \
                af[mt][0] = As[bi][base];                                 \
                af[mt][1] = As[bi][base + 160];                           \
                af[mt][2] = As[bi][base + 4];                             \
                af[mt][3] = As[bi][base + 164];                           \
            }                                                             \
            _Pragma("unroll")                                             \
            for (int nt = 0; nt < 8; nt++) {                              \
                uint32_t bf[2];                                           \
                int bb = (wn * 64 + nt * 8 + grp) * 20 + kk + thr;        \
                bf[0] = Bs[bi][bb];                                       \
                bf[1] = Bs[bi][bb + 4];                                   \
                _Pragma("unroll")                                         \
                for (int mt = 0; mt < 4; mt++)                            \
                    MMA_TF32(acc[mt][nt], af[mt], bf);                    \
            }                                                             \
        }                                                                 \
    } while (0)

    LDG_TILE(0);
    STS_TILE(0);
    __syncthreads();

    int cur = 0;
    for (int k0 = 16; k0 < K; k0 += 16) {
        LDG_TILE(k0);
        COMPUTE_TILE(cur);
        STS_TILE(cur ^ 1);
        __syncthreads();
        cur ^= 1;
    }
    COMPUTE_TILE(cur);

#pragma unroll
    for (int mt = 0; mt < 4; mt++) {
        const int row = rowA0 + wm * 64 + mt * 16 + grp;
#pragma unroll
        for (int nt = 0; nt < 8; nt++) {
            const int col = colB0 + wn * 64 + nt * 8 + thr * 2;
            float2 bz = *(const float2*)(bias + col);
            if (!TRANSV) {
                float2 v;
                v.x = acc[mt][nt][0] + bz.x;
                v.y = acc[mt][nt][1] + bz.y;
                *(float2*)(C + (size_t)row * N + col) = v;
                v.x = acc[mt][nt][2] + bz.x;
                v.y = acc[mt][nt][3] + bz.y;
                *(float2*)(C + (size_t)(row + 8) * N + col) = v;
            } else {
                // dst[((b*16+h)*64+d)*1024 + p]
                const int bx = row >> 10;
                const int p  = row & 1023;
                const size_t d0 = ((size_t)(bx * Hh + (col >> 6)) * Dh + (col & 63)) * Pp;
                const size_t d1 = d0 + Pp;  // col+1 stays in head (col even)
                C[d0 + p]     = acc[mt][nt][0] + bz.x;
                C[d1 + p]     = acc[mt][nt][1] + bz.y;
                C[d0 + p + 8] = acc[mt][nt][2] + bz.x;
                C[d1 + p + 8] = acc[mt][nt][3] + bz.y;
            }
        }
    }
#undef LDG_TILE
#undef STS_TILE
#undef COMPUTE_TILE
}

// Fused bilinear attention, tf32 mma. Block: one (b,h) x 128 queries,
// 4 warps, each warp 32 q-rows x 64 k-cols (192 B LDS per MMA).
#define ST 76
__global__ void __launch_bounds__(128, 2) attn_mma(
    const float* __restrict__ x, const float* __restrict__ watt,
    const float* __restrict__ bias, const float* __restrict__ vxT,
    float* __restrict__ outp)
{
    extern __shared__ uint32_t sm[];
    uint32_t* XWs = sm;                 // [128][ST] tf32 XW (scaled)
    uint32_t* Ps  = sm + 128 * ST;      // [128][ST] Xq then P tiles
    uint32_t* KVs = sm + 2 * 128 * ST;  // [64][ST]  W^T / Xk / V^T tiles

    const int tid  = threadIdx.x;
    const int lane = tid & 31;
    const int wid  = tid >> 5;       // 0..3
    const int grp  = lane >> 2;
    const int thr  = lane & 3;
    const int m0   = wid * 32;

    const int q0 = blockIdx.x * 128;
    const int bh = blockIdx.y;
    const int b  = bh >> 4;
    const int h  = bh & 15;

    const float* xb  = x + (size_t)b * Pp * Ee + h * Dh;
    const float* vtb = vxT + (size_t)bh * Dh * Pp;
    const float* bb  = bias + (size_t)h * Pp * Pp;

    // Phase 0: Xq -> Ps (tf32), W^T -> KVs (tf32)
#pragma unroll
    for (int r = 0; r < 16; r++) {
        int idx = tid + r * 128;
        int q = idx >> 4, c = (idx & 15) * 4;
        float4 v = *(const float4*)(xb + (size_t)(q0 + q) * Ee + c);
        uint4 t;
        t.x = f2tf(v.x); t.y = f2tf(v.y); t.z = f2tf(v.z); t.w = f2tf(v.w);
        *(uint4*)(&Ps[q * ST + c]) = t;
    }
    {
        const float* Wp = watt + (size_t)h * Dh * Dh;
#pragma unroll
        for (int r = 0; r < 8; r++) {
            int idx = tid + r * 128;
            int d = idx >> 4, e = (idx & 15) * 4;
            float4 v = *(const float4*)(Wp + d * Dh + e);
            KVs[(e + 0) * ST + d] = f2tf(v.x);
            KVs[(e + 1) * ST + d] = f2tf(v.y);
            KVs[(e + 2) * ST + d] = f2tf(v.z);
            KVs[(e + 3) * ST + d] = f2tf(v.w);
        }
    }
    __syncthreads();

    // Phase 1: XW = (Xq @ W) / 8 -> XWs
    {
        float c2[2][8][4];
#pragma unroll
        for (int mt = 0; mt < 2; mt++)
#pragma unroll
            for (int nt = 0; nt < 8; nt++)
#pragma unroll
                for (int r = 0; r < 4; r++) c2[mt][nt][r] = 0.f;
#pragma unroll
        for (int kk = 0; kk < 64; kk += 8) {
            uint32_t af[2][4];
#pragma unroll
            for (int mt = 0; mt < 2; mt++) {
                int base = (m0 + mt * 16 + grp) * ST + kk + thr;
                af[mt][0] = Ps[base];
                af[mt][1] = Ps[base + 8 * ST];
                af[mt][2] = Ps[base + 4];
                af[mt][3] = Ps[base + 8 * ST + 4];
            }
#pragma unroll
            for (int nt = 0; nt < 8; nt++) {
                uint32_t bf[2];
                bf[0] = KVs[(nt * 8 + grp) * ST + kk + thr];
                bf[1] = KVs[(nt * 8 + grp) * ST + kk + 4 + thr];
#pragma unroll
                for (int mt = 0; mt < 2; mt++)
                    MMA_TF32(c2[mt][nt], af[mt], bf);
            }
        }
        __syncthreads();  // Ps (Xq) reads complete before P overwrites later
#pragma unroll
        for (int mt = 0; mt < 2; mt++)
#pragma unroll
            for (int nt = 0; nt < 8; nt++) {
                int r0 = (m0 + mt * 16 + grp) * ST;
                int r1 = (m0 + mt * 16 + 8 + grp) * ST;
                XWs[r0 + nt * 8 + 2 * thr]     = f2tf(c2[mt][nt][0] * 0.125f);
                XWs[r0 + nt * 8 + 2 * thr + 1] = f2tf(c2[mt][nt][1] * 0.125f);
                XWs[r1 + nt * 8 + 2 * thr]     = f2tf(c2[mt][nt][2] * 0.125f);
                XWs[r1 + nt * 8 + 2 * thr + 1] = f2tf(c2[mt][nt][3] * 0.125f);
            }
    }
    __syncthreads();

    float o[2][8][4];
#pragma unroll
    for (int mt = 0; mt < 2; mt++)
#pragma unroll
        for (int dt = 0; dt < 8; dt++)
#pragma unroll
            for (int r = 0; r < 4; r++) o[mt][dt][r] = 0.f;
    // softmax state: index 2*mt + half  (half 0: rows +grp, half 1: rows +8+grp)
    float mr[4], lr[4];
#pragma unroll
    for (int i = 0; i < 4; i++) { mr[i] = -INFINITY; lr[i] = 0.f; }

    for (int kb = 0; kb < 16; kb++) {
        const int k0 = kb * 64;

        // Xk tile -> KVs
#pragma unroll
        for (int r = 0; r < 8; r++) {
            int idx = tid + r * 128;
            int k = idx >> 4, c = (idx & 15) * 4;
            float4 v = *(const float4*)(xb + (size_t)(k0 + k) * Ee + c);
            uint4 t;
            t.x = f2tf(v.x); t.y = f2tf(v.y); t.z = f2tf(v.z); t.w = f2tf(v.w);
            *(uint4*)(&KVs[k * ST + c]) = t;
        }
        __syncthreads();

        // S = XW @ Xk^T
        float s[2][8][4];
#pragma unroll
        for (int mt = 0; mt < 2; mt++)
#pragma unroll
            for (int nt = 0; nt < 8; nt++)
#pragma unroll
                for (int r = 0; r < 4; r++) s[mt][nt][r] = 0.f;
#pragma unroll
        for (int kk = 0; kk < 64; kk += 8) {
            uint32_t af[2][4];
#pragma unroll
            for (int mt = 0; mt < 2; mt++) {
                int base = (m0 + mt * 16 + grp) * ST + kk + thr;
                af[mt][0] = XWs[base];
                af[mt][1] = XWs[base + 8 * ST];
                af[mt][2] = XWs[base + 4];
                af[mt][3] = XWs[base + 8 * ST + 4];
            }
#pragma unroll
            for (int nt = 0; nt < 8; nt++) {
                uint32_t bf[2];
                bf[0] = KVs[(nt * 8 + grp) * ST + kk + thr];
                bf[1] = KVs[(nt * 8 + grp) * ST + kk + 4 + thr];
#pragma unroll
                for (int mt = 0; mt < 2; mt++)
                    MMA_TF32(s[mt][nt], af[mt], bf);
            }
        }

        // bias + online softmax (registers + quad shfl)
#pragma unroll
        for (int mt = 0; mt < 2; mt++) {
            const float* bp0 = bb + (size_t)(q0 + m0 + mt * 16 + grp) * Pp + k0;
            const float* bp1 = bp0 + 8 * Pp;
            float mx0 = -INFINITY, mx1 = -INFINITY;
#pragma unroll
            for (int nt = 0; nt < 8; nt++) {
                float2 bz0 = *(const float2*)(bp0 + nt * 8 + 2 * thr);
                float2 bz1 = *(const float2*)(bp1 + nt * 8 + 2 * thr);
                s[mt][nt][0] += bz0.x; s[mt][nt][1] += bz0.y;
                s[mt][nt][2] += bz1.x; s[mt][nt][3] += bz1.y;
                mx0 = fmaxf(mx0, fmaxf(s[mt][nt][0], s[mt][nt][1]));
                mx1 = fmaxf(mx1, fmaxf(s[mt][nt][2], s[mt][nt][3]));
            }
            mx0 = fmaxf(mx0, __shfl_xor_sync(0xffffffffu, mx0, 1));
            mx0 = fmaxf(mx0, __shfl_xor_sync(0xffffffffu, mx0, 2));
            mx1 = fmaxf(mx1, __shfl_xor_sync(0xffffffffu, mx1, 1));
            mx1 = fmaxf(mx1, __shfl_xor_sync(0xffffffffu, mx1, 2));
            const int i0 = 2 * mt, i1 = 2 * mt + 1;
            float mn0 = fmaxf(mr[i0], mx0), mn1 = fmaxf(mr[i1], mx1);
            float al0 = __expf(mr[i0] - mn0), al1 = __expf(mr[i1] - mn1);
            mr[i0] = mn0; mr[i1] = mn1;
            float ps0 = 0.f, ps1 = 0.f;
#pragma unroll
            for (int nt = 0; nt < 8; nt++) {
                s[mt][nt][0] = __expf(s[mt][nt][0] - mn0);
                s[mt][nt][1] = __expf(s[mt][nt][1] - mn0);
                s[mt][nt][2] = __expf(s[mt][nt][2] - mn1);
                s[mt][nt][3] = __expf(s[mt][nt][3] - mn1);
                ps0 += s[mt][nt][0] + s[mt][nt][1];
                ps1 += s[mt][nt][2] + s[mt][nt][3];
            }
            ps0 += __shfl_xor_sync(0xffffffffu, ps0, 1);
            ps0 += __shfl_xor_sync(0xffffffffu, ps0, 2);
            ps1 += __shfl_xor_sync(0xffffffffu, ps1, 1);
            ps1 += __shfl_xor_sync(0xffffffffu, ps1, 2);
            lr[i0] = lr[i0] * al0 + ps0;
            lr[i1] = lr[i1] * al1 + ps1;
#pragma unroll
            for (int dt = 0; dt < 8; dt++) {
                o[mt][dt][0] *= al0; o[mt][dt][1] *= al0;
                o[mt][dt][2] *= al1; o[mt][dt][3] *= al1;
            }
        }

        // P -> Ps (tf32)
#pragma unroll
        for (int mt = 0; mt < 2; mt++)
#pragma unroll
            for (int nt = 0; nt < 8; nt++) {
                int r0 = (m0 + mt * 16 + grp) * ST;
                int r1 = (m0 + mt * 16 + 8 + grp) * ST;
                Ps[r0 + nt * 8 + 2 * thr]     = f2tf(s[mt][nt][0]);
                Ps[r0 + nt * 8 + 2 * thr + 1] = f2tf(s[mt][nt][1]);
                Ps[r1 + nt * 8 + 2 * thr]     = f2tf(s[mt][nt][2]);
                Ps[r1 + nt * 8 + 2 * thr + 1] = f2tf(s[mt][nt][3]);
            }
        __syncthreads();

        // V^T tile -> KVs
#pragma unroll
        for (int r = 0; r < 8; r++) {
            int idx = tid + r * 128;
            int d = idx >> 4, c = (idx & 15) * 4;
            float4 v = *(const float4*)(vtb + (size_t)d * Pp + k0 + c);
            uint4 t;
            t.x = f2tf(v.x); t.y = f2tf(v.y); t.z = f2tf(v.z); t.w = f2tf(v.w);
            *(uint4*)(&KVs[d * ST + c]) = t;
        }
        __syncthreads();

        // O += P @ V
#pragma unroll
        for (int kk = 0; kk < 64; kk += 8) {
            uint32_t af[2][4];
#pragma unroll
            for (int mt = 0; mt < 2; mt++) {
                int base = (m0 + mt * 16 + grp) * ST + kk + thr;
                af[mt][0] = Ps[base];
                af[mt][1] = Ps[base + 8 * ST];
                af[mt][2] = Ps[base + 4];
                af[mt][3] = Ps[base + 8 * ST + 4];
            }
#pragma unroll
            for (int dt = 0; dt < 8; dt++) {
                uint32_t bf[2];
                bf[0] = KVs[(dt * 8 + grp) * ST + kk + thr];
                bf[1] = KVs[(dt * 8 + grp) * ST + kk + 4 + thr];
#pragma unroll
                for (int mt = 0; mt < 2; mt++)
                    MMA_TF32(o[mt][dt], af[mt], bf);
            }
        }
        __syncthreads();
    }

    // Normalize and write out (natural [b][p][e] layout)
    float* ob = outp + (size_t)b * Pp * Ee + h * Dh;
#pragma unroll
    for (int mt = 0; mt < 2; mt++) {
        const float li0 = 1.f / lr[2 * mt];
        const float li1 = 1.f / lr[2 * mt + 1];
        const int r0 = q0 + m0 + mt * 16 + grp;
#pragma unroll
        for (int dt = 0; dt < 8; dt++) {
            float2 v0, v1;
            v0.x = o[mt][dt][0] * li0; v0.y = o[mt][dt][1] * li0;
            v1.x = o[mt][dt][2] * li1; v1.y = o[mt][dt][3] * li1;
            *(float2*)(ob + (size_t)r0 * Ee + dt * 8 + 2 * thr) = v0;
            *(float2*)(ob + (size_t)(r0 + 8) * Ee + dt * 8 + 2 * thr) = v1;
        }
    }
}

extern "C" void kernel_launch(void* const* d_in, const int* in_sizes, int n_in,
                              void* d_out, int out_size) {
    const float* x     = (const float*)d_in[0];
    const float* watt  = (const float*)d_in[1];
    const float* abias = (const float*)d_in[2];
    const float* wv_w  = (const float*)d_in[3];
    const float* wv_b  = (const float*)d_in[4];
    const float* out_w = (const float*)d_in[5];
    const float* out_b = (const float*)d_in[6];
    float* outp = (float*)d_out;

    float *vxT = nullptr, *att = nullptr;
    cudaGetSymbolAddress((void**)&vxT, g_vxT);
    cudaGetSymbolAddress((void**)&att, g_att);

    const int attn_smem = 2 * 128 * ST * 4 + 64 * ST * 4;  // 97280 B
    cudaFuncSetAttribute(attn_mma, cudaFuncAttributeMaxDynamicSharedMemorySize,
                         attn_smem);

    dim3 gg(Ee / 128, (Bb * Pp) / 128);  // (8, 128)

    // 1) vxT[b][h][d][p] = (x @ wv_w^T + wv_b) transposed per head
    gemm_tf32<true><<<gg, 128>>>(x, wv_w, wv_b, vxT, Bb * Pp, Ee, Ee);
    // 2) fused bilinear attention (tf32 mma), 128-query tiles
    attn_mma<<<dim3(Pp / 128, Bb * Hh), 128, attn_smem>>>(x, watt, abias, vxT, att);
    // 3) out = att @ out_w^T + out_b
    gemm_tf32<false><<<gg, 128>>>(att, out_w, out_b, outp, Bb * Pp, Ee, Ee);
}

// round 6
// speedup vs baseline: 4.7151x; 1.4173x over previous
#include <cuda_runtime.h>
#include <cuda_fp16.h>
#include <math.h>
#include <stdint.h>

#define Bb 16
#define Pp 1024
#define Ee 1024
#define Hh 16
#define Dh 64

// Device-global scratch (allocation-free per harness rules)
__device__ float g_vxT[(size_t)Bb * Hh * Dh * Pp];  // vx transposed per head: [b][h][d][p]
__device__ float g_att[(size_t)Bb * Pp * Ee];       // attention output

__device__ __forceinline__ uint32_t pk(float a, float b) {
    __half2 h = __floats2half2_rn(a, b);
    return *(uint32_t*)&h;
}

#define MMA_F16(c, a, b)                                               \
    asm volatile(                                                      \
        "mma.sync.aligned.m16n8k16.row.col.f32.f16.f16.f32 "           \
        "{%0,%1,%2,%3}, {%4,%5,%6,%7}, {%8,%9}, {%0,%1,%2,%3};"        \
        : "+f"((c)[0]), "+f"((c)[1]), "+f"((c)[2]), "+f"((c)[3])       \
        : "r"((a)[0]), "r"((a)[1]), "r"((a)[2]), "r"((a)[3]),          \
          "r"((b)[0]), "r"((b)[1]))

// C[M,N] = A[M,K] @ B[N,K]^T + bias[N], fp16 mma (fp32 accum).
// 128x128 block, 8 warps as 2(m)x4(n), warp tile 64x32, K-tile 32,
// double-buffered smem. Rows: 16 u32 (32 fp16) + pad -> stride 20.
// TRANSV=true: write C transposed per 64-wide head: dst[b][h][d][p].
template <bool TRANSV>
__global__ void __launch_bounds__(256) gemm_fp16(
    const float* __restrict__ A, const float* __restrict__ Bw,
    const float* __restrict__ bias, float* __restrict__ C,
    int M, int N, int K)
{
    __shared__ uint32_t As[2][128 * 20];
    __shared__ uint32_t Bs[2][128 * 20];

    const int tid  = threadIdx.x;
    const int lane = tid & 31;
    const int wid  = tid >> 5;       // 0..7
    const int wm   = wid >> 2;       // 0..1
    const int wn   = wid & 3;        // 0..3
    const int grp  = lane >> 2;      // 0..7
    const int thr  = lane & 3;       // 0..3

    const int rowA0 = blockIdx.y * 128;
    const int colB0 = blockIdx.x * 128;

    // copy slots: r=0..3: flat=tid+r*256; row=flat>>3 (0..127), ch=flat&7
    int rw[4], ch[4];
#pragma unroll
    for (int r = 0; r < 4; r++) {
        int f = tid + r * 256;
        rw[r] = f >> 3;
        ch[r] = f & 7;
    }
    const float *Ap[4], *Bp[4];
#pragma unroll
    for (int r = 0; r < 4; r++) {
        Ap[r] = A  + (size_t)(rowA0 + rw[r]) * K + ch[r] * 4;
        Bp[r] = Bw + (size_t)(colB0 + rw[r]) * K + ch[r] * 4;
    }

    float acc[4][4][4];
#pragma unroll
    for (int mt = 0; mt < 4; mt++)
#pragma unroll
        for (int nt = 0; nt < 4; nt++)
#pragma unroll
            for (int r = 0; r < 4; r++) acc[mt][nt][r] = 0.f;

    float4 ra[4], rb[4];

#define LDG_TILE(k0)                                   \
    do {                                               \
        _Pragma("unroll")                              \
        for (int r = 0; r < 4; r++) {                  \
            ra[r] = *(const float4*)(Ap[r] + (k0));    \
            rb[r] = *(const float4*)(Bp[r] + (k0));    \
        }                                              \
    } while (0)

#define STS_TILE(bi)                                                      \
    do {                                                                  \
        _Pragma("unroll")                                                 \
        for (int r = 0; r < 4; r++) {                                     \
            int o = rw[r] * 20 + ch[r] * 2;                               \
            As[bi][o]     = pk(ra[r].x, ra[r].y);                         \
            As[bi][o + 1] = pk(ra[r].z, ra[r].w);                         \
            Bs[bi][o]     = pk(rb[r].x, rb[r].y);                         \
            Bs[bi][o + 1] = pk(rb[r].z, rb[r].w);                         \
        }                                                                 \
    } while (0)

#define COMPUTE_TILE(bi)                                                  \
    do {                                                                  \
        _Pragma("unroll")                                                 \
        for (int kk = 0; kk < 16; kk += 8) {                              \
            uint32_t af[4][4];                                            \
            _Pragma("unroll")                                             \
            for (int mt = 0; mt < 4; mt++) {                              \
                int base = (wm * 64 + mt * 16 + grp) * 20 + kk + thr;     \
                af[mt][0] = As[bi][base];                                 \
                af[mt][1] = As[bi][base + 160];                           \
                af[mt][2] = As[bi][base + 4];                             \
                af[mt][3] = As[bi][base + 164];                           \
            }                                                             \
            _Pragma("unroll")                                             \
            for (int nt = 0; nt < 4; nt++) {                              \
                uint32_t bf[2];                                           \
                int bb = (wn * 32 + nt * 8 + grp) * 20 + kk + thr;        \
                bf[0] = Bs[bi][bb];                                       \
                bf[1] = Bs[bi][bb + 4];                                   \
                _Pragma("unroll")                                         \
                for (int mt = 0; mt < 4; mt++)                            \
                    MMA_F16(acc[mt][nt], af[mt], bf);                     \
            }                                                             \
        }                                                                 \
    } while (0)

    LDG_TILE(0);
    STS_TILE(0);
    __syncthreads();

    int cur = 0;
    for (int k0 = 32; k0 < K; k0 += 32) {
        LDG_TILE(k0);
        COMPUTE_TILE(cur);
        STS_TILE(cur ^ 1);
        __syncthreads();
        cur ^= 1;
    }
    COMPUTE_TILE(cur);

#pragma unroll
    for (int mt = 0; mt < 4; mt++) {
        const int row = rowA0 + wm * 64 + mt * 16 + grp;
#pragma unroll
        for (int nt = 0; nt < 4; nt++) {
            const int col = colB0 + wn * 32 + nt * 8 + thr * 2;
            float2 bz = *(const float2*)(bias + col);
            if (!TRANSV) {
                float2 v;
                v.x = acc[mt][nt][0] + bz.x;
                v.y = acc[mt][nt][1] + bz.y;
                *(float2*)(C + (size_t)row * N + col) = v;
                v.x = acc[mt][nt][2] + bz.x;
                v.y = acc[mt][nt][3] + bz.y;
                *(float2*)(C + (size_t)(row + 8) * N + col) = v;
            } else {
                // dst[((b*16+h)*64+d)*1024 + p]
                const int bx = row >> 10;
                const int p  = row & 1023;
                const size_t d0 = ((size_t)(bx * Hh + (col >> 6)) * Dh + (col & 63)) * Pp;
                const size_t d1 = d0 + Pp;  // col+1 stays in head (col even)
                C[d0 + p]     = acc[mt][nt][0] + bz.x;
                C[d1 + p]     = acc[mt][nt][1] + bz.y;
                C[d0 + p + 8] = acc[mt][nt][2] + bz.x;
                C[d1 + p + 8] = acc[mt][nt][3] + bz.y;
            }
        }
    }
#undef LDG_TILE
#undef STS_TILE
#undef COMPUTE_TILE
}

// Fused bilinear attention, fp16 mma (fp32 accum + fp32 softmax).
// Block: one (b,h) x 128 queries, 4 warps, warp tile 32q x 64k.
// Rows: 32 u32 (64 fp16) + pad -> stride 36 u32 (conflict-free frags).
#define STP 36
__global__ void __launch_bounds__(128, 2) attn_mma(
    const float* __restrict__ x, const float* __restrict__ watt,
    const float* __restrict__ bias, const float* __restrict__ vxT,
    float* __restrict__ outp)
{
    extern __shared__ uint32_t sm[];
    uint32_t* XWs = sm;                  // [128][STP] fp16 XW (scaled)
    uint32_t* Ps  = sm + 128 * STP;      // [128][STP] Xq then P tiles
    uint32_t* KVs = sm + 2 * 128 * STP;  // [64][STP]  W^T / Xk / V^T tiles

    const int tid  = threadIdx.x;
    const int lane = tid & 31;
    const int wid  = tid >> 5;       // 0..3
    const int grp  = lane >> 2;
    const int thr  = lane & 3;
    const int m0   = wid * 32;

    const int q0 = blockIdx.x * 128;
    const int bh = blockIdx.y;
    const int b  = bh >> 4;
    const int h  = bh & 15;

    const float* xb  = x + (size_t)b * Pp * Ee + h * Dh;
    const float* vtb = vxT + (size_t)bh * Dh * Pp;
    const float* bb  = bias + (size_t)h * Pp * Pp;

    // Phase 0: Xq -> Ps (fp16 pairs), W^T -> KVs (half scatter)
#pragma unroll
    for (int r = 0; r < 16; r++) {
        int idx = tid + r * 128;
        int q = idx >> 4, c2 = (idx & 15) * 2;
        float4 v = *(const float4*)(xb + (size_t)(q0 + q) * Ee + c2 * 2);
        Ps[q * STP + c2]     = pk(v.x, v.y);
        Ps[q * STP + c2 + 1] = pk(v.z, v.w);
    }
    {
        const float* Wp = watt + (size_t)h * Dh * Dh;
        __half* KVh = (__half*)KVs;
#pragma unroll
        for (int r = 0; r < 8; r++) {
            int idx = tid + r * 128;
            int d = idx >> 4, e = (idx & 15) * 4;
            float4 v = *(const float4*)(Wp + d * Dh + e);
            KVh[(e + 0) * (2 * STP) + d] = __float2half_rn(v.x);
            KVh[(e + 1) * (2 * STP) + d] = __float2half_rn(v.y);
            KVh[(e + 2) * (2 * STP) + d] = __float2half_rn(v.z);
            KVh[(e + 3) * (2 * STP) + d] = __float2half_rn(v.w);
        }
    }
    __syncthreads();

    // Phase 1: XW = (Xq @ W) / 8 -> XWs (fp16)
    {
        float c2a[2][8][4];
#pragma unroll
        for (int mt = 0; mt < 2; mt++)
#pragma unroll
            for (int nt = 0; nt < 8; nt++)
#pragma unroll
                for (int r = 0; r < 4; r++) c2a[mt][nt][r] = 0.f;
#pragma unroll
        for (int kk = 0; kk < 32; kk += 8) {  // u32 units: covers d=0..63
            uint32_t af[2][4];
#pragma unroll
            for (int mt = 0; mt < 2; mt++) {
                int base = (m0 + mt * 16 + grp) * STP + kk + thr;
                af[mt][0] = Ps[base];
                af[mt][1] = Ps[base + 8 * STP];
                af[mt][2] = Ps[base + 4];
                af[mt][3] = Ps[base + 8 * STP + 4];
            }
#pragma unroll
            for (int nt = 0; nt < 8; nt++) {
                uint32_t bf[2];
                bf[0] = KVs[(nt * 8 + grp) * STP + kk + thr];
                bf[1] = KVs[(nt * 8 + grp) * STP + kk + 4 + thr];
#pragma unroll
                for (int mt = 0; mt < 2; mt++)
                    MMA_F16(c2a[mt][nt], af[mt], bf);
            }
        }
        __syncthreads();
#pragma unroll
        for (int mt = 0; mt < 2; mt++)
#pragma unroll
            for (int nt = 0; nt < 8; nt++) {
                int r0 = (m0 + mt * 16 + grp) * STP;
                int r1 = (m0 + mt * 16 + 8 + grp) * STP;
                XWs[r0 + nt * 4 + thr] = pk(c2a[mt][nt][0] * 0.125f,
                                            c2a[mt][nt][1] * 0.125f);
                XWs[r1 + nt * 4 + thr] = pk(c2a[mt][nt][2] * 0.125f,
                                            c2a[mt][nt][3] * 0.125f);
            }
    }
    __syncthreads();

    float o[2][8][4];
#pragma unroll
    for (int mt = 0; mt < 2; mt++)
#pragma unroll
        for (int dt = 0; dt < 8; dt++)
#pragma unroll
            for (int r = 0; r < 4; r++) o[mt][dt][r] = 0.f;
    float mr[4], lr[4];
#pragma unroll
    for (int i = 0; i < 4; i++) { mr[i] = -INFINITY; lr[i] = 0.f; }

    for (int kb = 0; kb < 16; kb++) {
        const int k0 = kb * 64;

        // Xk tile -> KVs
#pragma unroll
        for (int r = 0; r < 8; r++) {
            int idx = tid + r * 128;
            int k = idx >> 4, c2 = (idx & 15) * 2;
            float4 v = *(const float4*)(xb + (size_t)(k0 + k) * Ee + c2 * 2);
            KVs[k * STP + c2]     = pk(v.x, v.y);
            KVs[k * STP + c2 + 1] = pk(v.z, v.w);
        }
        __syncthreads();

        // S = XW @ Xk^T
        float s[2][8][4];
#pragma unroll
        for (int mt = 0; mt < 2; mt++)
#pragma unroll
            for (int nt = 0; nt < 8; nt++)
#pragma unroll
                for (int r = 0; r < 4; r++) s[mt][nt][r] = 0.f;
#pragma unroll
        for (int kk = 0; kk < 32; kk += 8) {
            uint32_t af[2][4];
#pragma unroll
            for (int mt = 0; mt < 2; mt++) {
                int base = (m0 + mt * 16 + grp) * STP + kk + thr;
                af[mt][0] = XWs[base];
                af[mt][1] = XWs[base + 8 * STP];
                af[mt][2] = XWs[base + 4];
                af[mt][3] = XWs[base + 8 * STP + 4];
            }
#pragma unroll
            for (int nt = 0; nt < 8; nt++) {
                uint32_t bf[2];
                bf[0] = KVs[(nt * 8 + grp) * STP + kk + thr];
                bf[1] = KVs[(nt * 8 + grp) * STP + kk + 4 + thr];
#pragma unroll
                for (int mt = 0; mt < 2; mt++)
                    MMA_F16(s[mt][nt], af[mt], bf);
            }
        }

        // bias + online softmax (fp32, quad shfl)
#pragma unroll
        for (int mt = 0; mt < 2; mt++) {
            const float* bp0 = bb + (size_t)(q0 + m0 + mt * 16 + grp) * Pp + k0;
            const float* bp1 = bp0 + 8 * Pp;
            float mx0 = -INFINITY, mx1 = -INFINITY;
#pragma unroll
            for (int nt = 0; nt < 8; nt++) {
                float2 bz0 = *(const float2*)(bp0 + nt * 8 + 2 * thr);
                float2 bz1 = *(const float2*)(bp1 + nt * 8 + 2 * thr);
                s[mt][nt][0] += bz0.x; s[mt][nt][1] += bz0.y;
                s[mt][nt][2] += bz1.x; s[mt][nt][3] += bz1.y;
                mx0 = fmaxf(mx0, fmaxf(s[mt][nt][0], s[mt][nt][1]));
                mx1 = fmaxf(mx1, fmaxf(s[mt][nt][2], s[mt][nt][3]));
            }
            mx0 = fmaxf(mx0, __shfl_xor_sync(0xffffffffu, mx0, 1));
            mx0 = fmaxf(mx0, __shfl_xor_sync(0xffffffffu, mx0, 2));
            mx1 = fmaxf(mx1, __shfl_xor_sync(0xffffffffu, mx1, 1));
            mx1 = fmaxf(mx1, __shfl_xor_sync(0xffffffffu, mx1, 2));
            const int i0 = 2 * mt, i1 = 2 * mt + 1;
            float mn0 = fmaxf(mr[i0], mx0), mn1 = fmaxf(mr[i1], mx1);
            float al0 = __expf(mr[i0] - mn0), al1 = __expf(mr[i1] - mn1);
            mr[i0] = mn0; mr[i1] = mn1;
            float ps0 = 0.f, ps1 = 0.f;
#pragma unroll
            for (int nt = 0; nt < 8; nt++) {
                s[mt][nt][0] = __expf(s[mt][nt][0] - mn0);
                s[mt][nt][1] = __expf(s[mt][nt][1] - mn0);
                s[mt][nt][2] = __expf(s[mt][nt][2] - mn1);
                s[mt][nt][3] = __expf(s[mt][nt][3] - mn1);
                ps0 += s[mt][nt][0] + s[mt][nt][1];
                ps1 += s[mt][nt][2] + s[mt][nt][3];
            }
            ps0 += __shfl_xor_sync(0xffffffffu, ps0, 1);
            ps0 += __shfl_xor_sync(0xffffffffu, ps0, 2);
            ps1 += __shfl_xor_sync(0xffffffffu, ps1, 1);
            ps1 += __shfl_xor_sync(0xffffffffu, ps1, 2);
            lr[i0] = lr[i0] * al0 + ps0;
            lr[i1] = lr[i1] * al1 + ps1;
#pragma unroll
            for (int dt = 0; dt < 8; dt++) {
                o[mt][dt][0] *= al0; o[mt][dt][1] *= al0;
                o[mt][dt][2] *= al1; o[mt][dt][3] *= al1;
            }
        }

        // P -> Ps (fp16 pairs; C-frag cols 2thr,2thr+1 pack naturally)
#pragma unroll
        for (int mt = 0; mt < 2; mt++)
#pragma unroll
            for (int nt = 0; nt < 8; nt++) {
                int r0 = (m0 + mt * 16 + grp) * STP;
                int r1 = (m0 + mt * 16 + 8 + grp) * STP;
                Ps[r0 + nt * 4 + thr] = pk(s[mt][nt][0], s[mt][nt][1]);
                Ps[r1 + nt * 4 + thr] = pk(s[mt][nt][2], s[mt][nt][3]);
            }
        __syncthreads();

        // V^T tile -> KVs
#pragma unroll
        for (int r = 0; r < 8; r++) {
            int idx = tid + r * 128;
            int d = idx >> 4, c2 = (idx & 15) * 2;
            float4 v = *(const float4*)(vtb + (size_t)d * Pp + k0 + c2 * 2);
            KVs[d * STP + c2]     = pk(v.x, v.y);
            KVs[d * STP + c2 + 1] = pk(v.z, v.w);
        }
        __syncthreads();

        // O += P @ V
#pragma unroll
        for (int kk = 0; kk < 32; kk += 8) {
            uint32_t af[2][4];
#pragma unroll
            for (int mt = 0; mt < 2; mt++) {
                int base = (m0 + mt * 16 + grp) * STP + kk + thr;
                af[mt][0] = Ps[base];
                af[mt][1] = Ps[base + 8 * STP];
                af[mt][2] = Ps[base + 4];
                af[mt][3] = Ps[base + 8 * STP + 4];
            }
#pragma unroll
            for (int dt = 0; dt < 8; dt++) {
                uint32_t bf[2];
                bf[0] = KVs[(dt * 8 + grp) * STP + kk + thr];
                bf[1] = KVs[(dt * 8 + grp) * STP + kk + 4 + thr];
#pragma unroll
                for (int mt = 0; mt < 2; mt++)
                    MMA_F16(o[mt][dt], af[mt], bf);
            }
        }
        __syncthreads();
    }

    // Normalize and write out (natural [b][p][e] layout)
    float* ob = outp + (size_t)b * Pp * Ee + h * Dh;
#pragma unroll
    for (int mt = 0; mt < 2; mt++) {
        const float li0 = 1.f / lr[2 * mt];
        const float li1 = 1.f / lr[2 * mt + 1];
        const int r0 = q0 + m0 + mt * 16 + grp;
#pragma unroll
        for (int dt = 0; dt < 8; dt++) {
            float2 v0, v1;
            v0.x = o[mt][dt][0] * li0; v0.y = o[mt][dt][1] * li0;
            v1.x = o[mt][dt][2] * li1; v1.y = o[mt][dt][3] * li1;
            *(float2*)(ob + (size_t)r0 * Ee + dt * 8 + 2 * thr) = v0;
            *(float2*)(ob + (size_t)(r0 + 8) * Ee + dt * 8 + 2 * thr) = v1;
        }
    }
}

extern "C" void kernel_launch(void* const* d_in, const int* in_sizes, int n_in,
                              void* d_out, int out_size) {
    const float* x     = (const float*)d_in[0];
    const float* watt  = (const float*)d_in[1];
    const float* abias = (const float*)d_in[2];
    const float* wv_w  = (const float*)d_in[3];
    const float* wv_b  = (const float*)d_in[4];
    const float* out_w = (const float*)d_in[5];
    const float* out_b = (const float*)d_in[6];
    float* outp = (float*)d_out;

    float *vxT = nullptr, *att = nullptr;
    cudaGetSymbolAddress((void**)&vxT, g_vxT);
    cudaGetSymbolAddress((void**)&att, g_att);

    const int attn_smem = (2 * 128 + 64) * STP * 4;  // 46080 B
    cudaFuncSetAttribute(attn_mma, cudaFuncAttributeMaxDynamicSharedMemorySize,
                         attn_smem);

    dim3 gg(Ee / 128, (Bb * Pp) / 128);  // (8, 128)

    // 1) vxT[b][h][d][p] = (x @ wv_w^T + wv_b) transposed per head
    gemm_fp16<true><<<gg, 256>>>(x, wv_w, wv_b, vxT, Bb * Pp, Ee, Ee);
    // 2) fused bilinear attention (fp16 mma), 128-query tiles
    attn_mma<<<dim3(Pp / 128, Bb * Hh), 128, attn_smem>>>(x, watt, abias, vxT, att);
    // 3) out = att @ out_w^T + out_b
    gemm_fp16<false><<<gg, 256>>>(att, out_w, out_b, outp, Bb * Pp, Ee, Ee);
}

// round 11
// speedup vs baseline: 5.1107x; 1.0839x over previous
#include <cuda_runtime.h>
#include <cuda_fp16.h>
#include <math.h>
#include <stdint.h>

#define Bb 16
#define Pp 1024
#define Ee 1024
#define Hh 16
#define Dh 64

// Device-global scratch (allocation-free per harness rules)
__device__ __half g_xh[(size_t)Bb * Pp * Ee];        // x as fp16
__device__ __half g_wvh[(size_t)Ee * Ee];            // wv_w as fp16
__device__ __half g_owh[(size_t)Ee * Ee];            // out_w as fp16
__device__ __half g_vxT[(size_t)Bb * Hh * Dh * Pp];  // vx fp16, per head: [b][h][d][p]
__device__ __half g_att[(size_t)Bb * Pp * Ee];       // attention out fp16

__device__ __forceinline__ uint32_t pk(float a, float b) {
    __half2 h = __floats2half2_rn(a, b);
    return *(uint32_t*)&h;
}

#define MMA_F16(c, a, b)                                               \
    asm volatile(                                                      \
        "mma.sync.aligned.m16n8k16.row.col.f32.f16.f16.f32 "           \
        "{%0,%1,%2,%3}, {%4,%5,%6,%7}, {%8,%9}, {%0,%1,%2,%3};"        \
        : "+f"((c)[0]), "+f"((c)[1]), "+f"((c)[2]), "+f"((c)[3])       \
        : "r"((a)[0]), "r"((a)[1]), "r"((a)[2]), "r"((a)[3]),          \
          "r"((b)[0]), "r"((b)[1]))

// fp32 -> fp16 elementwise (8 per thread, grid-stride)
__global__ void cvt_fp16(const float* __restrict__ s, __half* __restrict__ d,
                         int n) {
    for (int i = (blockIdx.x * blockDim.x + threadIdx.x) * 8; i < n;
         i += gridDim.x * blockDim.x * 8) {
        float4 a = *(const float4*)(s + i);
        float4 b = *(const float4*)(s + i + 4);
        uint4 o;
        o.x = pk(a.x, a.y); o.y = pk(a.z, a.w);
        o.z = pk(b.x, b.y); o.w = pk(b.z, b.w);
        *(uint4*)(d + i) = o;
    }
}

// C[M,N] = A[M,K] @ B[N,K]^T + bias[N], fp16 inputs, fp32 accum.
// 128x128 block, 8 warps as 2(m)x4(n), warp tile 64x32, K-tile 32,
// double-buffered smem (R6-proven structure). Row pitch 20 u32.
// TRANSV=true: C fp16, transposed per 64-wide head: dst[b][h][d][p].
// TRANSV=false: C fp32 row-major.
template <bool TRANSV>
__global__ void __launch_bounds__(256) gemm_fp16(
    const __half* __restrict__ A, const __half* __restrict__ Bw,
    const float* __restrict__ bias, void* __restrict__ Cv,
    int M, int N, int K)
{
    __shared__ uint32_t As[2][128 * 20];
    __shared__ uint32_t Bs[2][128 * 20];

    const int tid  = threadIdx.x;
    const int lane = tid & 31;
    const int wid  = tid >> 5;       // 0..7
    const int wm   = wid >> 2;       // 0..1
    const int wn   = wid & 3;        // 0..3
    const int grp  = lane >> 2;      // 0..7
    const int thr  = lane & 3;       // 0..3

    const int rowA0 = blockIdx.y * 128;
    const int colB0 = blockIdx.x * 128;

    // K-tile = 32 halves = 4 uint4 chunks/row; 128 rows x 4 = 512 slots,
    // 256 threads x 2. chunk f = tid + r*256: row f>>2, chunk f&3.
    int rw[2], ch[2];
#pragma unroll
    for (int r = 0; r < 2; r++) {
        int f = tid + r * 256;
        rw[r] = f >> 2;
        ch[r] = f & 3;
    }
    const __half *Ap[2], *Bp[2];
#pragma unroll
    for (int r = 0; r < 2; r++) {
        Ap[r] = A  + (size_t)(rowA0 + rw[r]) * K + ch[r] * 8;
        Bp[r] = Bw + (size_t)(colB0 + rw[r]) * K + ch[r] * 8;
    }

    float acc[4][4][4];
#pragma unroll
    for (int mt = 0; mt < 4; mt++)
#pragma unroll
        for (int nt = 0; nt < 4; nt++)
#pragma unroll
            for (int r = 0; r < 4; r++) acc[mt][nt][r] = 0.f;

    uint4 ra[2], rb[2];

#define LDG_TILE(k0)                                   \
    do {                                               \
        _Pragma("unroll")                              \
        for (int r = 0; r < 2; r++) {                  \
            ra[r] = *(const uint4*)(Ap[r] + (k0));     \
            rb[r] = *(const uint4*)(Bp[r] + (k0));     \
        }                                              \
    } while (0)

#define STS_TILE(bi)                                                      \
    do {                                                                  \
        _Pragma("unroll")                                                 \
        for (int r = 0; r < 2; r++) {                                     \
            *(uint4*)(&As[bi][rw[r] * 20 + ch[r] * 4]) = ra[r];           \
            *(uint4*)(&Bs[bi][rw[r] * 20 + ch[r] * 4]) = rb[r];           \
        }                                                                 \
    } while (0)

#define COMPUTE_TILE(bi)                                                  \
    do {                                                                  \
        _Pragma("unroll")                                                 \
        for (int kk = 0; kk < 16; kk += 8) {                              \
            uint32_t af[4][4];                                            \
            _Pragma("unroll")                                             \
            for (int mt = 0; mt < 4; mt++) {                              \
                int base = (wm * 64 + mt * 16 + grp) * 20 + kk + thr;     \
                af[mt][0] = As[bi][base];                                 \
                af[mt][1] = As[bi][base + 160];                           \
                af[mt][2] = As[bi][base + 4];                             \
                af[mt][3] = As[bi][base + 164];                           \
            }                                                             \
            _Pragma("unroll")                                             \
            for (int nt = 0; nt < 4; nt++) {                              \
                uint32_t bf[2];                                           \
                int bb = (wn * 32 + nt * 8 + grp) * 20 + kk + thr;        \
                bf[0] = Bs[bi][bb];                                       \
                bf[1] = Bs[bi][bb + 4];                                   \
                _Pragma("unroll")                                         \
                for (int mt = 0; mt < 4; mt++)                            \
                    MMA_F16(acc[mt][nt], af[mt], bf);                     \
            }                                                             \
        }                                                                 \
    } while (0)

    LDG_TILE(0);
    STS_TILE(0);
    __syncthreads();

    int cur = 0;
    for (int k0 = 32; k0 < K; k0 += 32) {
        LDG_TILE(k0);
        COMPUTE_TILE(cur);
        STS_TILE(cur ^ 1);
        __syncthreads();
        cur ^= 1;
    }
    COMPUTE_TILE(cur);

#pragma unroll
    for (int mt = 0; mt < 4; mt++) {
        const int row = rowA0 + wm * 64 + mt * 16 + grp;
#pragma unroll
        for (int nt = 0; nt < 4; nt++) {
            const int col = colB0 + wn * 32 + nt * 8 + thr * 2;
            float2 bz = *(const float2*)(bias + col);
            if (!TRANSV) {
                float* C = (float*)Cv;
                float2 v;
                v.x = acc[mt][nt][0] + bz.x;
                v.y = acc[mt][nt][1] + bz.y;
                *(float2*)(C + (size_t)row * N + col) = v;
                v.x = acc[mt][nt][2] + bz.x;
                v.y = acc[mt][nt][3] + bz.y;
                *(float2*)(C + (size_t)(row + 8) * N + col) = v;
            } else {
                __half* C = (__half*)Cv;
                const int bx = row >> 10;
                const int p  = row & 1023;
                const size_t d0 = ((size_t)(bx * Hh + (col >> 6)) * Dh + (col & 63)) * Pp;
                const size_t d1 = d0 + Pp;  // col+1 stays in head (col even)
                C[d0 + p]     = __float2half_rn(acc[mt][nt][0] + bz.x);
                C[d1 + p]     = __float2half_rn(acc[mt][nt][1] + bz.y);
                C[d0 + p + 8] = __float2half_rn(acc[mt][nt][2] + bz.x);
                C[d1 + p + 8] = __float2half_rn(acc[mt][nt][3] + bz.y);
            }
        }
    }
#undef LDG_TILE
#undef STS_TILE
#undef COMPUTE_TILE
}

// Fused bilinear attention, fp16 mma (fp32 accum + fp32 softmax).
// One (b,h) x 128 queries per block, 4 warps (32q x 64k warp tile).
// Tile rows are 64 halves = 8 uint4 chunks (fill maps fixed from R9).
#define STP 36
__global__ void __launch_bounds__(128, 2) attn_mma(
    const __half* __restrict__ xh, const float* __restrict__ watt,
    const float* __restrict__ bias, const __half* __restrict__ vxT,
    __half* __restrict__ outp)
{
    extern __shared__ uint32_t sm[];
    uint32_t* XWs = sm;                  // [128][STP] fp16 XW (scaled)
    uint32_t* Ps  = sm + 128 * STP;      // [128][STP] Xq then P tiles
    uint32_t* KVs = sm + 2 * 128 * STP;  // [64][STP]  W^T / Xk / V^T tiles

    const int tid  = threadIdx.x;
    const int lane = tid & 31;
    const int wid  = tid >> 5;       // 0..3
    const int grp  = lane >> 2;
    const int thr  = lane & 3;
    const int m0   = wid * 32;

    const int q0 = blockIdx.x * 128;
    const int bh = blockIdx.y;
    const int b  = bh >> 4;
    const int h  = bh & 15;

    const __half* xb  = xh + (size_t)b * Pp * Ee + h * Dh;
    const __half* vtb = vxT + (size_t)bh * Dh * Pp;
    const float*  bb  = bias + (size_t)h * Pp * Pp;

    // Phase 0: Xq -> Ps. 128 rows x 8 chunks = 1024 slots = 128 thr x 8.
#pragma unroll
    for (int r = 0; r < 8; r++) {
        int f = tid + r * 128;
        int q = f >> 3, c = f & 7;           // c: 8-half (16B) chunk
        *(uint4*)(&Ps[q * STP + c * 4]) =
            *(const uint4*)(xb + (size_t)(q0 + q) * Ee + c * 8);
    }
    {
        const float* Wp = watt + (size_t)h * Dh * Dh;
        __half* KVh = (__half*)KVs;
#pragma unroll
        for (int r = 0; r < 8; r++) {
            int idx = tid + r * 128;
            int d = idx >> 4, e = (idx & 15) * 4;
            float4 v = *(const float4*)(Wp + d * Dh + e);
            KVh[(e + 0) * (2 * STP) + d] = __float2half_rn(v.x);
            KVh[(e + 1) * (2 * STP) + d] = __float2half_rn(v.y);
            KVh[(e + 2) * (2 * STP) + d] = __float2half_rn(v.z);
            KVh[(e + 3) * (2 * STP) + d] = __float2half_rn(v.w);
        }
    }
    __syncthreads();

    // Phase 1: XW = (Xq @ W) / 8 -> XWs (fp16)
    {
        float c2a[2][8][4];
#pragma unroll
        for (int mt = 0; mt < 2; mt++)
#pragma unroll
            for (int nt = 0; nt < 8; nt++)
#pragma unroll
                for (int r = 0; r < 4; r++) c2a[mt][nt][r] = 0.f;
#pragma unroll
        for (int kk = 0; kk < 32; kk += 8) {
            uint32_t af[2][4];
#pragma unroll
            for (int mt = 0; mt < 2; mt++) {
                int base = (m0 + mt * 16 + grp) * STP + kk + thr;
                af[mt][0] = Ps[base];
                af[mt][1] = Ps[base + 8 * STP];
                af[mt][2] = Ps[base + 4];
                af[mt][3] = Ps[base + 8 * STP + 4];
            }
#pragma unroll
            for (int nt = 0; nt < 8; nt++) {
                uint32_t bf[2];
                bf[0] = KVs[(nt * 8 + grp) * STP + kk + thr];
                bf[1] = KVs[(nt * 8 + grp) * STP + kk + 4 + thr];
#pragma unroll
                for (int mt = 0; mt < 2; mt++)
                    MMA_F16(c2a[mt][nt], af[mt], bf);
            }
        }
        __syncthreads();
#pragma unroll
        for (int mt = 0; mt < 2; mt++)
#pragma unroll
            for (int nt = 0; nt < 8; nt++) {
                int r0 = (m0 + mt * 16 + grp) * STP;
                int r1 = (m0 + mt * 16 + 8 + grp) * STP;
                XWs[r0 + nt * 4 + thr] = pk(c2a[mt][nt][0] * 0.125f,
                                            c2a[mt][nt][1] * 0.125f);
                XWs[r1 + nt * 4 + thr] = pk(c2a[mt][nt][2] * 0.125f,
                                            c2a[mt][nt][3] * 0.125f);
            }
    }
    __syncthreads();

    float o[2][8][4];
#pragma unroll
    for (int mt = 0; mt < 2; mt++)
#pragma unroll
        for (int dt = 0; dt < 8; dt++)
#pragma unroll
            for (int r = 0; r < 4; r++) o[mt][dt][r] = 0.f;
    float mr[4], lr[4];
#pragma unroll
    for (int i = 0; i < 4; i++) { mr[i] = -INFINITY; lr[i] = 0.f; }

    for (int kb = 0; kb < 16; kb++) {
        const int k0 = kb * 64;

        // Xk tile -> KVs. 64 rows x 8 chunks = 512 slots = 128 thr x 4.
#pragma unroll
        for (int r = 0; r < 4; r++) {
            int f = tid + r * 128;
            int k = f >> 3, c = f & 7;
            *(uint4*)(&KVs[k * STP + c * 4]) =
                *(const uint4*)(xb + (size_t)(k0 + k) * Ee + c * 8);
        }
        __syncthreads();

        // S = XW @ Xk^T
        float s[2][8][4];
#pragma unroll
        for (int mt = 0; mt < 2; mt++)
#pragma unroll
            for (int nt = 0; nt < 8; nt++)
#pragma unroll
                for (int r = 0; r < 4; r++) s[mt][nt][r] = 0.f;
#pragma unroll
        for (int kk = 0; kk < 32; kk += 8) {
            uint32_t af[2][4];
#pragma unroll
            for (int mt = 0; mt < 2; mt++) {
                int base = (m0 + mt * 16 + grp) * STP + kk + thr;
                af[mt][0] = XWs[base];
                af[mt][1] = XWs[base + 8 * STP];
                af[mt][2] = XWs[base + 4];
                af[mt][3] = XWs[base + 8 * STP + 4];
            }
#pragma unroll
            for (int nt = 0; nt < 8; nt++) {
                uint32_t bf[2];
                bf[0] = KVs[(nt * 8 + grp) * STP + kk + thr];
                bf[1] = KVs[(nt * 8 + grp) * STP + kk + 4 + thr];
#pragma unroll
                for (int mt = 0; mt < 2; mt++)
                    MMA_F16(s[mt][nt], af[mt], bf);
            }
        }

        // bias + online softmax (fp32, quad shfl)
#pragma unroll
        for (int mt = 0; mt < 2; mt++) {
            const float* bp0 = bb + (size_t)(q0 + m0 + mt * 16 + grp) * Pp + k0;
            const float* bp1 = bp0 + 8 * Pp;
            float mx0 = -INFINITY, mx1 = -INFINITY;
#pragma unroll
            for (int nt = 0; nt < 8; nt++) {
                float2 bz0 = *(const float2*)(bp0 + nt * 8 + 2 * thr);
                float2 bz1 = *(const float2*)(bp1 + nt * 8 + 2 * thr);
                s[mt][nt][0] += bz0.x; s[mt][nt][1] += bz0.y;
                s[mt][nt][2] += bz1.x; s[mt][nt][3] += bz1.y;
                mx0 = fmaxf(mx0, fmaxf(s[mt][nt][0], s[mt][nt][1]));
                mx1 = fmaxf(mx1, fmaxf(s[mt][nt][2], s[mt][nt][3]));
            }
            mx0 = fmaxf(mx0, __shfl_xor_sync(0xffffffffu, mx0, 1));
            mx0 = fmaxf(mx0, __shfl_xor_sync(0xffffffffu, mx0, 2));
            mx1 = fmaxf(mx1, __shfl_xor_sync(0xffffffffu, mx1, 1));
            mx1 = fmaxf(mx1, __shfl_xor_sync(0xffffffffu, mx1, 2));
            const int i0 = 2 * mt, i1 = 2 * mt + 1;
            float mn0 = fmaxf(mr[i0], mx0), mn1 = fmaxf(mr[i1], mx1);
            float al0 = __expf(mr[i0] - mn0), al1 = __expf(mr[i1] - mn1);
            mr[i0] = mn0; mr[i1] = mn1;
            float ps0 = 0.f, ps1 = 0.f;
#pragma unroll
            for (int nt = 0; nt < 8; nt++) {
                s[mt][nt][0] = __expf(s[mt][nt][0] - mn0);
                s[mt][nt][1] = __expf(s[mt][nt][1] - mn0);
                s[mt][nt][2] = __expf(s[mt][nt][2] - mn1);
                s[mt][nt][3] = __expf(s[mt][nt][3] - mn1);
                ps0 += s[mt][nt][0] + s[mt][nt][1];
                ps1 += s[mt][nt][2] + s[mt][nt][3];
            }
            ps0 += __shfl_xor_sync(0xffffffffu, ps0, 1);
            ps0 += __shfl_xor_sync(0xffffffffu, ps0, 2);
            ps1 += __shfl_xor_sync(0xffffffffu, ps1, 1);
            ps1 += __shfl_xor_sync(0xffffffffu, ps1, 2);
            lr[i0] = lr[i0] * al0 + ps0;
            lr[i1] = lr[i1] * al1 + ps1;
#pragma unroll
            for (int dt = 0; dt < 8; dt++) {
                o[mt][dt][0] *= al0; o[mt][dt][1] *= al0;
                o[mt][dt][2] *= al1; o[mt][dt][3] *= al1;
            }
        }

        // P -> Ps (fp16 pairs)
#pragma unroll
        for (int mt = 0; mt < 2; mt++)
#pragma unroll
            for (int nt = 0; nt < 8; nt++) {
                int r0 = (m0 + mt * 16 + grp) * STP;
                int r1 = (m0 + mt * 16 + 8 + grp) * STP;
                Ps[r0 + nt * 4 + thr] = pk(s[mt][nt][0], s[mt][nt][1]);
                Ps[r1 + nt * 4 + thr] = pk(s[mt][nt][2], s[mt][nt][3]);
            }
        __syncthreads();

        // V^T tile -> KVs. 64 rows x 8 chunks = 512 slots.
#pragma unroll
        for (int r = 0; r < 4; r++) {
            int f = tid + r * 128;
            int d = f >> 3, c = f & 7;
            *(uint4*)(&KVs[d * STP + c * 4]) =
                *(const uint4*)(vtb + (size_t)d * Pp + k0 + c * 8);
        }
        __syncthreads();

        // O += P @ V
#pragma unroll
        for (int kk = 0; kk < 32; kk += 8) {
            uint32_t af[2][4];
#pragma unroll
            for (int mt = 0; mt < 2; mt++) {
                int base = (m0 + mt * 16 + grp) * STP + kk + thr;
                af[mt][0] = Ps[base];
                af[mt][1] = Ps[base + 8 * STP];
                af[mt][2] = Ps[base + 4];
                af[mt][3] = Ps[base + 8 * STP + 4];
            }
#pragma unroll
            for (int dt = 0; dt < 8; dt++) {
                uint32_t bf[2];
                bf[0] = KVs[(dt * 8 + grp) * STP + kk + thr];
                bf[1] = KVs[(dt * 8 + grp) * STP + kk + 4 + thr];
#pragma unroll
                for (int mt = 0; mt < 2; mt++)
                    MMA_F16(o[mt][dt], af[mt], bf);
            }
        }
        __syncthreads();
    }

    // Normalize and write out as fp16, natural [b][p][e] layout
    __half* ob = outp + (size_t)b * Pp * Ee + h * Dh;
#pragma unroll
    for (int mt = 0; mt < 2; mt++) {
        const float li0 = 1.f / lr[2 * mt];
        const float li1 = 1.f / lr[2 * mt + 1];
        const int r0 = q0 + m0 + mt * 16 + grp;
#pragma unroll
        for (int dt = 0; dt < 8; dt++) {
            *(uint32_t*)(ob + (size_t)r0 * Ee + dt * 8 + 2 * thr) =
                pk(o[mt][dt][0] * li0, o[mt][dt][1] * li0);
            *(uint32_t*)(ob + (size_t)(r0 + 8) * Ee + dt * 8 + 2 * thr) =
                pk(o[mt][dt][2] * li1, o[mt][dt][3] * li1);
        }
    }
}

extern "C" void kernel_launch(void* const* d_in, const int* in_sizes, int n_in,
                              void* d_out, int out_size) {
    const float* x     = (const float*)d_in[0];
    const float* watt  = (const float*)d_in[1];
    const float* abias = (const float*)d_in[2];
    const float* wv_w  = (const float*)d_in[3];
    const float* wv_b  = (const float*)d_in[4];
    const float* out_w = (const float*)d_in[5];
    const float* out_b = (const float*)d_in[6];
    float* outp = (float*)d_out;

    __half *xhp, *wvhp, *owhp, *vxTp, *attp;
    cudaGetSymbolAddress((void**)&xhp, g_xh);
    cudaGetSymbolAddress((void**)&wvhp, g_wvh);
    cudaGetSymbolAddress((void**)&owhp, g_owh);
    cudaGetSymbolAddress((void**)&vxTp, g_vxT);
    cudaGetSymbolAddress((void**)&attp, g_att);

    const int attn_smem = (2 * 128 + 64) * STP * 4;  // 46080 B
    cudaFuncSetAttribute(attn_mma, cudaFuncAttributeMaxDynamicSharedMemorySize,
                         attn_smem);

    // 0) one-time fp16 conversions
    cvt_fp16<<<2048, 256>>>(x, xhp, Bb * Pp * Ee);
    cvt_fp16<<<512, 256>>>(wv_w, wvhp, Ee * Ee);
    cvt_fp16<<<512, 256>>>(out_w, owhp, Ee * Ee);

    dim3 gg(Ee / 128, (Bb * Pp) / 128);  // (8, 128)

    // 1) vxT[b][h][d][p] (fp16) = (x @ wv_w^T + wv_b) transposed per head
    gemm_fp16<true><<<gg, 256>>>(xhp, wvhp, wv_b, vxTp, Bb * Pp, Ee, Ee);
    // 2) fused bilinear attention (fp16 mma), output fp16
    attn_mma<<<dim3(Pp / 128, Bb * Hh), 128, attn_smem>>>(xhp, watt, abias,
                                                          vxTp, attp);
    // 3) out = att @ out_w^T + out_b (fp32 out)
    gemm_fp16<false><<<gg, 256>>>(attp, owhp, out_b, outp, Bb * Pp, Ee, Ee);
}